// round 13
// baseline (speedup 1.0000x reference)
#include <cuda_runtime.h>
#include <cuda_bf16.h>
#include <cstdint>

#define NPTS 4096
#define CCH  128
#define BB   2
#define KNB  9
#define OC   256
#define OC2  512

// -------- scratch (no allocation allowed) --------
__device__ __nv_bfloat16 g_ab[(size_t)BB*NPTS*256];  // per point: [hi(128) | lo(128)] of normalized x
__device__ __nv_bfloat16 g_wb[(size_t)OC2*256];      // per out-channel: [hi(128) | lo(128)] of wct
__device__ float g_sq[BB*NPTS];                      // squared norms of normalized pts
__device__ float g_nrm[BB*NPTS];                     // scale s*inv (~||x||)
__device__ float g_y[(size_t)BB*NPTS*OC2];           // (B,N,512): [0:256]=p, [256:512]=q
__device__ int   g_nn[BB*NPTS*KNB];                  // knn indices
__device__ unsigned long long g_nnk[(size_t)BB*2*NPTS*KNB]; // per-half top-9 keys

#define CP_COMMIT() asm volatile("cp.async.commit_group;" ::: "memory")
#define CP_WAIT0()  asm volatile("cp.async.wait_group 0;" ::: "memory")
__device__ __forceinline__ void cp16(uint32_t dst, const void* src) {
    asm volatile("cp.async.cg.shared.global [%0], [%1], 16;" :: "r"(dst), "l"(src) : "memory");
}

// ---------------- prep: normalize, split to bf16 hi/lo (transposed), sq, nrm ----------------
__global__ void __launch_bounds__(128) prep_kernel(const float* __restrict__ x) {
    extern __shared__ float psm[];
    float* sm   = psm;            // [128][129]
    float* invs = psm + 128*129;  // [128]
    const int b = blockIdx.y, n0 = blockIdx.x * 128, tid = threadIdx.x;
    const float* xb = x + (size_t)b * CCH * NPTS;

    for (int i = tid; i < 128 * 128; i += 128) {
        int c = i >> 7, n = i & 127;
        sm[c * 129 + n] = xb[c * NPTS + n0 + n];
    }
    __syncthreads();

    float s = 0.f;
    #pragma unroll 8
    for (int c = 0; c < 128; ++c) { float v = sm[c * 129 + tid]; s = fmaf(v, v, s); }
    float inv = rsqrtf(s + 1e-12f);
    g_sq[b * NPTS + n0 + tid]  = s * inv * inv;
    g_nrm[b * NPTS + n0 + tid] = s * inv;
    invs[tid] = inv;
    __syncthreads();

    const int wid = tid >> 5, l = tid & 31;
    for (int p = wid; p < 128; p += 4) {
        float ip = invs[p];
        __nv_bfloat16 hi[4], lo[4];
        #pragma unroll
        for (int q = 0; q < 4; ++q) {
            float v = sm[(4 * l + q) * 129 + p] * ip;
            hi[q] = __float2bfloat16(v);
            lo[q] = __float2bfloat16(v - __bfloat162float(hi[q]));
        }
        __nv_bfloat16* dst = g_ab + (size_t)(b * NPTS + n0 + p) * 256;
        *(uint2*)(dst + 4 * l)       = *(uint2*)hi;
        *(uint2*)(dst + 128 + 4 * l) = *(uint2*)lo;
    }
}

// ---------------- prep: combined weight, bf16 hi/lo, layout [o][hi128|lo128] ----------------
__global__ void wprep_kernel(const float* __restrict__ w) {
    int i = blockIdx.x * 256 + threadIdx.x;
    if (i >= OC2 * CCH) return;
    int o = i >> 7, c = i & 127;
    float v;
    if (o < OC) v = w[o * 256 + c] - w[o * 256 + 128 + c];   // w1 - w2
    else        v = w[(o - OC) * 256 + 128 + c];             // w2
    __nv_bfloat16 hi = __float2bfloat16(v);
    __nv_bfloat16 lo = __float2bfloat16(v - __bfloat162float(hi));
    g_wb[(size_t)o * 256 + c]       = hi;
    g_wb[(size_t)o * 256 + 128 + c] = lo;
}

// ---------------- shared helpers ----------------
__device__ __forceinline__ unsigned long long packKey(float v, unsigned idx) {
    unsigned u = __float_as_uint(v);
    u = (u & 0x80000000u) ? ~u : (u | 0x80000000u);   // order-preserving float->uint
    return ((unsigned long long)u << 32) | (0xFFFFFFFFu - idx);
}
__device__ __forceinline__ float unpackVal(unsigned long long k) {
    unsigned u = (unsigned)(k >> 32);
    u = (u & 0x80000000u) ? (u & 0x7FFFFFFFu) : ~u;
    return __uint_as_float(u);
}
#define TK_INIT 0x0080000000000000ull   // packKey(-FLT_MAX, 0xFFFFFFFF)

__device__ __forceinline__ void tkInsert(unsigned long long* tk, unsigned long long key) {
    if (key > tk[8]) {
        #pragma unroll
        for (int i = 0; i < 9; ++i) {
            unsigned long long a = tk[i];
            bool g = key > a;
            tk[i] = g ? key : a;
            key   = g ? a : key;
        }
    }
}
__device__ __forceinline__ void mma_bf16(float* c,
        uint32_t a0, uint32_t a1, uint32_t a2, uint32_t a3,
        uint32_t b0, uint32_t b1) {
    asm volatile(
        "mma.sync.aligned.m16n8k16.row.col.f32.bf16.bf16.f32 "
        "{%0,%1,%2,%3},{%4,%5,%6,%7},{%8,%9},{%0,%1,%2,%3};"
        : "+f"(c[0]), "+f"(c[1]), "+f"(c[2]), "+f"(c[3])
        : "r"(a0), "r"(a1), "r"(a2), "r"(a3), "r"(b0), "r"(b1));
}
__device__ __forceinline__ void ldsm4(uint32_t* r, uint32_t addr) {
    asm volatile("ldmatrix.sync.aligned.m8n8.x4.shared.b16 {%0,%1,%2,%3}, [%4];"
        : "=r"(r[0]), "=r"(r[1]), "=r"(r[2]), "=r"(r[3]) : "r"(addr));
}

// 512B-row XOR-swizzled tile: byte offset of 16B chunk j (0..31) in row r
__device__ __forceinline__ uint32_t swz512(int r, int j) {
    return (uint32_t)(r * 512 + (((j & 24) | ((j ^ r) & 7)) << 4));
}

// ================= knn: 128x128 CTA tile, 512 threads, col-split across 2 CTAs =================
// smem: A tile [128 rows x 512B] @0, B double buffer 2x65536 @65536, sqm 2x128f @196608.
// Ssc overlays B[cur].
#define KS_A   0
#define KS_B   65536
#define KS_SQM 196608
#define KNN_SMEM 197632
#define NCHUNK 16   // 2048 cols per CTA / 128
#define KNT 512

__device__ __forceinline__ void knn_issueB(int b, int m0, uint32_t bufAddr, uint32_t sqmAddr, int tid) {
    const uint4* abG = (const uint4*)g_ab;
    #pragma unroll 4
    for (int i = tid; i < 128 * 32; i += KNT) {
        int r = i >> 5, j = i & 31;
        cp16(bufAddr + swz512(r, j), abG + (size_t)(b * NPTS + m0 + r) * 32 + j);
    }
    if (tid < 32)
        cp16(sqmAddr + tid * 16, g_sq + b * NPTS + m0 + tid * 4);
    CP_COMMIT();
}

__global__ void __launch_bounds__(KNT, 1)
knn_kernel() {
    extern __shared__ char smraw[];
    const uint32_t smem_base = (uint32_t)__cvta_generic_to_shared(smraw);
    const uint32_t asAddr  = smem_base + KS_A;
    const uint32_t bAddr0  = smem_base + KS_B;
    const uint32_t sqmAddr = smem_base + KS_SQM;
    float* sqmF = (float*)(smraw + KS_SQM);

    const int tid = threadIdx.x, wid = tid >> 5, l = tid & 31;
    const int b = blockIdx.z, half = blockIdx.y, n0 = blockIdx.x * 128;
    const int colBase = half * 2048;

    // prologue: A tile + B chunk0 + sqm0, one cp.async group
    {
        const uint4* abG = (const uint4*)g_ab;
        #pragma unroll 2
        for (int i = tid; i < 128 * 32; i += KNT) {
            int r = i >> 5, j = i & 31;
            cp16(asAddr + swz512(r, j), abG + (size_t)(b * NPTS + n0 + r) * 32 + j);
        }
    }
    knn_issueB(b, colBase, bAddr0, sqmAddr, tid);

    const int wm = wid & 3, wn = wid >> 2;        // 4x4 warp grid, warp tile 32x32
    const int g = l >> 2, t = l & 3;
    const int lr = l & 15, lc4 = l >> 4, lb = (l >> 3) & 1, l7 = l & 7;
    const int rB = tid >> 2, cs = tid & 3;        // topk: 4 threads per row, 32 cols each
    const int rb7 = rB & 7;
    const int bP0 = wn * 32 + lc4 * 8 + l7;

    unsigned long long tk[9];
    #pragma unroll
    for (int i = 0; i < 9; ++i) tk[i] = TK_INIT;
    float thr = -3.402823466e38f;

    for (int chunk = 0; chunk < NCHUNK; ++chunk) {
        const int cur = chunk & 1;
        const int m0  = colBase + chunk * 128;

        CP_WAIT0();          // B[cur] + sqm[cur] resident
        __syncthreads();     // everyone sees it; prev Ssc (in B[1-cur]) reads done

        if (chunk + 1 < NCHUNK)   // next load -> B[1-cur], overlaps MMA+scatter+topk
            knn_issueB(b, m0 + 128, bAddr0 + (unsigned)(1 - cur) * 65536,
                       sqmAddr + (unsigned)(1 - cur) * 512, tid);

        const uint32_t bC = bAddr0 + (unsigned)cur * 65536;

        float acc[2][4][4];
        #pragma unroll
        for (int mi = 0; mi < 2; ++mi)
            #pragma unroll
            for (int ni = 0; ni < 4; ++ni)
                #pragma unroll
                for (int q = 0; q < 4; ++q) acc[mi][ni][q] = 0.f;

        // emulated-fp32 K=384: (hi,hi)+(hi,lo)+(lo,hi); 16B chunks 0-15 = hi, 16-31 = lo
        #pragma unroll
        for (int seg = 0; seg < 3; ++seg) {
            const int ja0 = (seg == 2) ? 16 : 0;
            const int jb0 = (seg == 1) ? 16 : 0;
            #pragma unroll
            for (int kk = 0; kk < 8; ++kk) {
                const int ja = ja0 + kk * 2 + lc4;
                const int jb = jb0 + kk * 2 + lb;
                uint32_t a[2][4], b0[4], b1[4];
                #pragma unroll
                for (int mi = 0; mi < 2; ++mi)
                    ldsm4(a[mi], asAddr + swz512(wm * 32 + mi * 16 + lr, ja));
                ldsm4(b0, bC + swz512(bP0, jb));
                ldsm4(b1, bC + swz512(bP0 + 16, jb));
                #pragma unroll
                for (int mi = 0; mi < 2; ++mi) {
                    mma_bf16(acc[mi][0], a[mi][0], a[mi][1], a[mi][2], a[mi][3], b0[0], b0[1]);
                    mma_bf16(acc[mi][1], a[mi][0], a[mi][1], a[mi][2], a[mi][3], b0[2], b0[3]);
                    mma_bf16(acc[mi][2], a[mi][0], a[mi][1], a[mi][2], a[mi][3], b1[0], b1[1]);
                    mma_bf16(acc[mi][3], a[mi][0], a[mi][1], a[mi][2], a[mi][3], b1[2], b1[3]);
                }
            }
        }

        __syncthreads();     // all MMA reads of B[cur] done -> Ssc may overlay it

        // scatter rank values (2*inner - sq_m; the -sq_r term is row-constant, rank-invariant)
        char* ssc = smraw + KS_B + (size_t)cur * 65536;
        const float* sqc = sqmF + cur * 128;
        #pragma unroll
        for (int mi = 0; mi < 2; ++mi) {
            int r0 = wm * 32 + mi * 16 + g;
            #pragma unroll
            for (int ni = 0; ni < 4; ++ni) {
                int C = wn * 32 + ni * 8 + t * 2;
                int lc = C >> 2;
                float2 sm2 = *(const float2*)&sqc[C];
                float* a = acc[mi][ni];
                uint32_t sw = (uint32_t)((((lc & 24) | ((lc & 7) ^ (r0 & 7))) << 4) + (t & 1) * 8);
                *(float2*)(ssc + r0 * 512 + sw) =
                    make_float2(fmaf(2.f, a[0], -sm2.x), fmaf(2.f, a[1], -sm2.y));
                *(float2*)(ssc + (r0 + 8) * 512 + sw) =
                    make_float2(fmaf(2.f, a[2], -sm2.x), fmaf(2.f, a[3], -sm2.y));
            }
        }
        __syncthreads();

        // top-9: each thread scans 32 cols of its fixed row, float-threshold gated
        #pragma unroll
        for (int j4 = 0; j4 < 8; ++j4) {
            int lc = cs * 8 + j4;
            const float4 v = *(const float4*)(ssc + rB * 512
                                              + (((lc & 24) | ((lc & 7) ^ rb7)) << 4));
            float m = fmaxf(fmaxf(v.x, v.y), fmaxf(v.z, v.w));
            if (m >= thr) {   // rare after warm-up; >= keeps exact tie handling
                float vv[4] = {v.x, v.y, v.z, v.w};
                #pragma unroll
                for (int q = 0; q < 4; ++q)
                    if (vv[q] >= thr)
                        tkInsert(tk, packKey(vv[q], (unsigned)(m0 + lc * 4 + q)));
                thr = unpackVal(tk[8]);
            }
        }
    }

    // merge the four col-slices of each row (4-lane shfl segments), write keys
    for (int k = 0; k < KNB; ++k) {
        unsigned long long m = tk[0];
        #pragma unroll
        for (int d = 2; d; d >>= 1) {
            unsigned long long o = __shfl_down_sync(0xffffffffu, m, d, 4);
            if (o > m) m = o;
        }
        m = __shfl_sync(0xffffffffu, m, 0, 4);
        if (tk[0] == m) {    // keys unique: exactly one lane pops
            #pragma unroll
            for (int i = 0; i < 8; ++i) tk[i] = tk[i + 1];
            tk[8] = 0ull;
        }
        if (cs == 0)
            g_nnk[((size_t)(b * 2 + half) * NPTS + n0 + rB) * KNB + k] = m;
    }
}

// ---------------- merge the two column-halves' top-9 lists ----------------
__global__ void nnmerge_kernel() {
    int i = blockIdx.x * 256 + threadIdx.x;
    if (i >= BB * NPTS) return;
    int b = i >> 12, row = i & (NPTS - 1);
    const unsigned long long* k0 = g_nnk + ((size_t)(b * 2 + 0) * NPTS + row) * KNB;
    const unsigned long long* k1 = g_nnk + ((size_t)(b * 2 + 1) * NPTS + row) * KNB;
    unsigned long long tk[9];
    #pragma unroll
    for (int k = 0; k < KNB; ++k) tk[k] = k0[k];
    #pragma unroll
    for (int k = 0; k < KNB; ++k) tkInsert(tk, k1[k]);
    #pragma unroll
    for (int k = 0; k < KNB; ++k)
        g_nn[(b * NPTS + row) * KNB + k] = (int)(0xFFFFFFFFu - (unsigned)tk[k]);
}

// ================= p/q GEMM (round-7 proven): y[b][n][o] = (wct[o].xn[n])*nrm[n] =================
#define KM   64
#define KN   128
#define KSTR 264
#define KROWB 528

__device__ __forceinline__ void gmma_block(float acc[2][4][4], uint32_t aAddr, uint32_t bAddr) {
    #pragma unroll
    for (int seg = 0; seg < 3; ++seg) {
        const int aoff = (seg == 2) ? 256 : 0;
        const int boff = (seg == 1) ? 256 : 0;
        #pragma unroll
        for (int kk = 0; kk < 8; ++kk) {
            uint32_t a[2][4], bq[2][4];
            ldsm4(a[0], aAddr + aoff + kk * 32);
            ldsm4(a[1], aAddr + 16 * KROWB + aoff + kk * 32);
            ldsm4(bq[0], bAddr + boff + kk * 32);
            ldsm4(bq[1], bAddr + 16 * KROWB + boff + kk * 32);
            #pragma unroll
            for (int mi = 0; mi < 2; ++mi) {
                mma_bf16(acc[mi][0], a[mi][0], a[mi][1], a[mi][2], a[mi][3], bq[0][0], bq[0][1]);
                mma_bf16(acc[mi][1], a[mi][0], a[mi][1], a[mi][2], a[mi][3], bq[0][2], bq[0][3]);
                mma_bf16(acc[mi][2], a[mi][0], a[mi][1], a[mi][2], a[mi][3], bq[1][0], bq[1][1]);
                mma_bf16(acc[mi][3], a[mi][0], a[mi][1], a[mi][2], a[mi][3], bq[1][2], bq[1][3]);
            }
        }
    }
}
__device__ __forceinline__ void gemm_issueW(int o0, uint32_t bsAddr, int tid) {
    const uint4* wbG = (const uint4*)g_wb;
    #pragma unroll 4
    for (int i = tid; i < KN * 32; i += 256) {
        int r = i >> 5, j = i & 31;
        cp16(bsAddr + (unsigned)(r * 33 + j) * 16, wbG + (size_t)(o0 + r) * 32 + j);
    }
    CP_COMMIT();
}

__global__ void __launch_bounds__(256, 1)
gemm_kernel() {
    extern __shared__ char smraw[];
    __nv_bfloat16* As  = (__nv_bfloat16*)smraw;       // [64][264]  (points)
    __nv_bfloat16* Bs0 = As + KM * KSTR;              // 2 x [128][264] (wct)
    float* nrmr = (float*)(Bs0 + 2 * KN * KSTR);      // [64]

    const int tid = threadIdx.x;
    const int b   = blockIdx.y;
    const int n0  = blockIdx.x * KM;
    const uint4* __restrict__ abG = (const uint4*)g_ab;

    const uint32_t asAddr  = (uint32_t)__cvta_generic_to_shared(As);
    const uint32_t bsAddr0 = (uint32_t)__cvta_generic_to_shared(Bs0);
    gemm_issueW(0, bsAddr0, tid);

    for (int i = tid; i < KM * 32; i += 256) {
        int r = i >> 5, j = i & 31;
        ((uint4*)As)[r * 33 + j] = abG[(size_t)(b * NPTS + n0 + r) * 32 + j];
    }
    if (tid < KM) nrmr[tid] = g_nrm[b * NPTS + n0 + tid];

    const int wid = tid >> 5, l = tid & 31;
    const int wm = wid & 1, wn = wid >> 1;
    const int g = l >> 2, t = l & 3;

    const uint32_t aFrag = asAddr + (unsigned)(wm * 32 + (l & 15)) * KROWB + (unsigned)(l >> 4) * 16;
    const uint32_t bFragOff = (unsigned)(wn * 32 + (l >> 4) * 8 + (l & 7)) * KROWB
                            + (unsigned)((l >> 3) & 1) * 16;

    float* yb = g_y + (size_t)b * NPTS * OC2;

    for (int chunk = 0; chunk < OC2 / KN; ++chunk) {
        const int cur = chunk & 1;
        CP_WAIT0();
        __syncthreads();
        if (chunk + 1 < OC2 / KN)
            gemm_issueW((chunk + 1) * KN, bsAddr0 + (unsigned)(1 - cur) * KN * KROWB, tid);

        float acc[2][4][4];
        #pragma unroll
        for (int mi = 0; mi < 2; ++mi)
            #pragma unroll
            for (int ni = 0; ni < 4; ++ni)
                #pragma unroll
                for (int q = 0; q < 4; ++q) acc[mi][ni][q] = 0.f;

        gmma_block(acc, aFrag, bsAddr0 + (unsigned)cur * KN * KROWB + bFragOff);

        const int oc = chunk * KN;
        #pragma unroll
        for (int mi = 0; mi < 2; ++mi) {
            int r = wm * 32 + mi * 16 + g;
            float nr0 = nrmr[r], nr1 = nrmr[r + 8];
            #pragma unroll
            for (int ni = 0; ni < 4; ++ni) {
                int c = wn * 32 + ni * 8 + t * 2;
                float* a = acc[mi][ni];
                *(float2*)&yb[(size_t)(n0 + r) * OC2 + oc + c] =
                    make_float2(a[0] * nr0, a[1] * nr0);
                *(float2*)&yb[(size_t)(n0 + r + 8) * OC2 + oc + c] =
                    make_float2(a[2] * nr1, a[3] * nr1);
            }
        }
        __syncthreads();
    }
}

// ---------------- epilogue: gather + max + relu ----------------
__global__ void final_kernel(const float* __restrict__ bias, float* __restrict__ out) {
    __shared__ int sj[KNB];
    const int n = blockIdx.x;
    const int b = blockIdx.y;
    const int o = threadIdx.x;
    if (o < KNB) sj[o] = g_nn[(b * NPTS + n) * KNB + o];
    __syncthreads();
    const float* yb = g_y + (size_t)b * NPTS * OC2;
    float p = yb[(size_t)n * OC2 + o];
    float best = -3.4e38f;
    #pragma unroll
    for (int k = 0; k < KNB; ++k)
        best = fmaxf(best, yb[(size_t)sj[k] * OC2 + OC + o]);
    float v = fmaxf(p + best + bias[o], 0.f);
    out[((size_t)b * OC + o) * NPTS + n] = v;
}

// ---------------- launch ----------------
extern "C" void kernel_launch(void* const* d_in, const int* in_sizes, int n_in,
                              void* d_out, int out_size) {
    const float* x    = (const float*)d_in[0];
    const float* w    = (const float*)d_in[1];
    const float* bias = (const float*)d_in[2];
    float* out = (float*)d_out;

    const int prep_smem = (128 * 129 + 128) * (int)sizeof(float);       // 66560
    const int gemm_smem = KM*KSTR*2 + 2*KN*KSTR*2 + KM * 4;             // 169216
    cudaFuncSetAttribute(prep_kernel, cudaFuncAttributeMaxDynamicSharedMemorySize, prep_smem);
    cudaFuncSetAttribute(knn_kernel,  cudaFuncAttributeMaxDynamicSharedMemorySize, KNN_SMEM);
    cudaFuncSetAttribute(gemm_kernel, cudaFuncAttributeMaxDynamicSharedMemorySize, gemm_smem);

    prep_kernel   <<<dim3(NPTS / 128, BB), 128, prep_smem>>>(x);
    wprep_kernel  <<<(OC2 * CCH + 255) / 256, 256>>>(w);
    gemm_kernel   <<<dim3(NPTS / KM, BB), 256, gemm_smem>>>();
    knn_kernel    <<<dim3(NPTS / 128, 2, BB), KNT, KNN_SMEM>>>();
    nnmerge_kernel<<<(BB * NPTS + 255) / 256, 256>>>();
    final_kernel  <<<dim3(NPTS, BB), 256>>>(bias, out);
}

// round 14
// speedup vs baseline: 1.1821x; 1.1821x over previous
#include <cuda_runtime.h>
#include <cuda_bf16.h>
#include <cstdint>

#define NPTS 4096
#define CCH  128
#define BB   2
#define KNB  9
#define OC   256
#define OC2  512

// -------- scratch (no allocation allowed) --------
__device__ __nv_bfloat16 g_ab[(size_t)BB*NPTS*256];  // per point: [hi(128) | lo(128)] of normalized x
__device__ __nv_bfloat16 g_wb[(size_t)OC2*256];      // per out-channel: [hi(128) | lo(128)] of wct
__device__ float g_sq[BB*NPTS];                      // squared norms of normalized pts
__device__ float g_nrm[BB*NPTS];                     // scale s*inv (~||x||)
__device__ float g_y[(size_t)BB*NPTS*OC2];           // (B,N,512): [0:256]=p, [256:512]=q
__device__ int   g_nn[BB*NPTS*KNB];                  // knn indices
__device__ unsigned long long g_nnk[(size_t)BB*2*NPTS*KNB]; // per-half top-9 keys

#define CP_COMMIT() asm volatile("cp.async.commit_group;" ::: "memory")
#define CP_WAIT0()  asm volatile("cp.async.wait_group 0;" ::: "memory")
__device__ __forceinline__ void cp16(uint32_t dst, const void* src) {
    asm volatile("cp.async.cg.shared.global [%0], [%1], 16;" :: "r"(dst), "l"(src) : "memory");
}

// ---------------- prep: normalize, split to bf16 hi/lo (transposed), sq, nrm ----------------
__global__ void __launch_bounds__(128) prep_kernel(const float* __restrict__ x) {
    extern __shared__ float psm[];
    float* sm   = psm;            // [128][129]
    float* invs = psm + 128*129;  // [128]
    const int b = blockIdx.y, n0 = blockIdx.x * 128, tid = threadIdx.x;
    const float* xb = x + (size_t)b * CCH * NPTS;

    for (int i = tid; i < 128 * 128; i += 128) {
        int c = i >> 7, n = i & 127;
        sm[c * 129 + n] = xb[c * NPTS + n0 + n];
    }
    __syncthreads();

    float s = 0.f;
    #pragma unroll 8
    for (int c = 0; c < 128; ++c) { float v = sm[c * 129 + tid]; s = fmaf(v, v, s); }
    float inv = rsqrtf(s + 1e-12f);
    g_sq[b * NPTS + n0 + tid]  = s * inv * inv;
    g_nrm[b * NPTS + n0 + tid] = s * inv;
    invs[tid] = inv;
    __syncthreads();

    const int wid = tid >> 5, l = tid & 31;
    for (int p = wid; p < 128; p += 4) {
        float ip = invs[p];
        __nv_bfloat16 hi[4], lo[4];
        #pragma unroll
        for (int q = 0; q < 4; ++q) {
            float v = sm[(4 * l + q) * 129 + p] * ip;
            hi[q] = __float2bfloat16(v);
            lo[q] = __float2bfloat16(v - __bfloat162float(hi[q]));
        }
        __nv_bfloat16* dst = g_ab + (size_t)(b * NPTS + n0 + p) * 256;
        *(uint2*)(dst + 4 * l)       = *(uint2*)hi;
        *(uint2*)(dst + 128 + 4 * l) = *(uint2*)lo;
    }
}

// ---------------- prep: combined weight, bf16 hi/lo, layout [o][hi128|lo128] ----------------
__global__ void wprep_kernel(const float* __restrict__ w) {
    int i = blockIdx.x * 256 + threadIdx.x;
    if (i >= OC2 * CCH) return;
    int o = i >> 7, c = i & 127;
    float v;
    if (o < OC) v = w[o * 256 + c] - w[o * 256 + 128 + c];   // w1 - w2
    else        v = w[(o - OC) * 256 + 128 + c];             // w2
    __nv_bfloat16 hi = __float2bfloat16(v);
    __nv_bfloat16 lo = __float2bfloat16(v - __bfloat162float(hi));
    g_wb[(size_t)o * 256 + c]       = hi;
    g_wb[(size_t)o * 256 + 128 + c] = lo;
}

// ---------------- shared helpers ----------------
__device__ __forceinline__ unsigned long long packKey(float v, unsigned idx) {
    unsigned u = __float_as_uint(v);
    u = (u & 0x80000000u) ? ~u : (u | 0x80000000u);   // order-preserving float->uint
    return ((unsigned long long)u << 32) | (0xFFFFFFFFu - idx);
}
__device__ __forceinline__ float unpackVal(unsigned long long k) {
    unsigned u = (unsigned)(k >> 32);
    u = (u & 0x80000000u) ? (u & 0x7FFFFFFFu) : ~u;
    return __uint_as_float(u);
}
#define TK_INIT 0x0080000000000000ull   // packKey(-FLT_MAX, 0xFFFFFFFF)

__device__ __forceinline__ void tkInsert(unsigned long long* tk, unsigned long long key) {
    if (key > tk[8]) {
        #pragma unroll
        for (int i = 0; i < 9; ++i) {
            unsigned long long a = tk[i];
            bool g = key > a;
            tk[i] = g ? key : a;
            key   = g ? a : key;
        }
    }
}
__device__ __forceinline__ void mma_bf16(float* c,
        uint32_t a0, uint32_t a1, uint32_t a2, uint32_t a3,
        uint32_t b0, uint32_t b1) {
    asm volatile(
        "mma.sync.aligned.m16n8k16.row.col.f32.bf16.bf16.f32 "
        "{%0,%1,%2,%3},{%4,%5,%6,%7},{%8,%9},{%0,%1,%2,%3};"
        : "+f"(c[0]), "+f"(c[1]), "+f"(c[2]), "+f"(c[3])
        : "r"(a0), "r"(a1), "r"(a2), "r"(a3), "r"(b0), "r"(b1));
}
__device__ __forceinline__ void ldsm4(uint32_t* r, uint32_t addr) {
    asm volatile("ldmatrix.sync.aligned.m8n8.x4.shared.b16 {%0,%1,%2,%3}, [%4];"
        : "=r"(r[0]), "=r"(r[1]), "=r"(r[2]), "=r"(r[3]) : "r"(addr));
}

// ================= knn: 128x128 CTA tile, padded 528B rows (NO xor swizzle) =================
// smem: A [128 x 528B] @0, B double buffer 2 x [128 x 528B] @67584, sqm 2x128f @202752.
// Ssc overlays B[cur] (128 floats = 512B fit in the 528B row).
#define KROWB 528
#define KTILE 67584            // 128 * 528
#define KS_B   67584
#define KS_SQM 202752
#define KNN_SMEM 203776
#define NCHUNK 16              // 2048 cols per CTA / 128

__device__ __forceinline__ void knn_issueB(int b, int m0, uint32_t bufAddr, uint32_t sqmAddr, int tid) {
    const uint4* abG = (const uint4*)g_ab;
    #pragma unroll 4
    for (int i = tid; i < 128 * 32; i += 256) {
        int r = i >> 5, j = i & 31;
        cp16(bufAddr + (unsigned)(r * 33 + j) * 16, abG + (size_t)(b * NPTS + m0 + r) * 32 + j);
    }
    if (tid < 32)
        cp16(sqmAddr + tid * 16, g_sq + b * NPTS + m0 + tid * 4);
    CP_COMMIT();
}

__global__ void __launch_bounds__(256, 1)
knn_kernel() {
    extern __shared__ char smraw[];
    const uint32_t smem_base = (uint32_t)__cvta_generic_to_shared(smraw);
    const uint32_t asAddr  = smem_base;
    const uint32_t bAddr0  = smem_base + KS_B;
    const uint32_t sqmAddr = smem_base + KS_SQM;
    float* sqmF = (float*)(smraw + KS_SQM);

    const int tid = threadIdx.x, wid = tid >> 5, l = tid & 31;
    const int b = blockIdx.z, half = blockIdx.y, n0 = blockIdx.x * 128;
    const int colBase = half * 2048;

    // prologue: A tile + B chunk0 + sqm0, one cp.async group
    {
        const uint4* abG = (const uint4*)g_ab;
        #pragma unroll 4
        for (int i = tid; i < 128 * 32; i += 256) {
            int r = i >> 5, j = i & 31;
            cp16(asAddr + (unsigned)(r * 33 + j) * 16, abG + (size_t)(b * NPTS + n0 + r) * 32 + j);
        }
    }
    knn_issueB(b, colBase, bAddr0, sqmAddr, tid);

    const int wm = wid & 1, wn = wid >> 1;        // 2x4 warp grid, warp tile 64x32
    const int g = l >> 2, t = l & 3;
    const int rB = tid >> 1, cs = tid & 1;        // topk: 2 threads per row, 64 cols each

    // per-thread ldsm fragment bases (padded layout: plain strides, no swizzle)
    const uint32_t aFrag = asAddr + (unsigned)(wm * 64 + (l & 15)) * KROWB + (unsigned)(l >> 4) * 16;
    const uint32_t bFragOff = (unsigned)(wn * 32 + (l >> 4) * 8 + (l & 7)) * KROWB
                            + (unsigned)((l >> 3) & 1) * 16;

    unsigned long long tk[9];
    #pragma unroll
    for (int i = 0; i < 9; ++i) tk[i] = TK_INIT;
    float thr = -3.402823466e38f;

    for (int chunk = 0; chunk < NCHUNK; ++chunk) {
        const int cur = chunk & 1;
        const int m0  = colBase + chunk * 128;

        CP_WAIT0();          // B[cur] + sqm[cur] resident
        __syncthreads();     // everyone sees it; prev Ssc (in B[1-cur]) reads done

        if (chunk + 1 < NCHUNK)   // next load -> B[1-cur], overlaps MMA+scatter+topk
            knn_issueB(b, m0 + 128, bAddr0 + (unsigned)(1 - cur) * KTILE,
                       sqmAddr + (unsigned)(1 - cur) * 512, tid);

        const uint32_t bFrag = bAddr0 + (unsigned)cur * KTILE + bFragOff;

        float acc[4][4][4];
        #pragma unroll
        for (int mi = 0; mi < 4; ++mi)
            #pragma unroll
            for (int ni = 0; ni < 4; ++ni)
                #pragma unroll
                for (int q = 0; q < 4; ++q) acc[mi][ni][q] = 0.f;

        // emulated-fp32 K=384: (hi,hi)+(hi,lo)+(lo,hi); lo half at +256 bytes in the row
        #pragma unroll
        for (int seg = 0; seg < 3; ++seg) {
            const int aoff = (seg == 2) ? 256 : 0;
            const int boff = (seg == 1) ? 256 : 0;
            #pragma unroll
            for (int kk = 0; kk < 8; ++kk) {
                uint32_t a[4][4], b0[4], b1[4];
                #pragma unroll
                for (int mi = 0; mi < 4; ++mi)
                    ldsm4(a[mi], aFrag + (unsigned)(mi * 16 * KROWB) + aoff + kk * 32);
                ldsm4(b0, bFrag + boff + kk * 32);
                ldsm4(b1, bFrag + 16 * KROWB + boff + kk * 32);
                #pragma unroll
                for (int mi = 0; mi < 4; ++mi) {
                    mma_bf16(acc[mi][0], a[mi][0], a[mi][1], a[mi][2], a[mi][3], b0[0], b0[1]);
                    mma_bf16(acc[mi][1], a[mi][0], a[mi][1], a[mi][2], a[mi][3], b0[2], b0[3]);
                    mma_bf16(acc[mi][2], a[mi][0], a[mi][1], a[mi][2], a[mi][3], b1[0], b1[1]);
                    mma_bf16(acc[mi][3], a[mi][0], a[mi][1], a[mi][2], a[mi][3], b1[2], b1[3]);
                }
            }
        }

        __syncthreads();     // all MMA reads of B[cur] done -> Ssc may overlay it

        // scatter rank values (2*inner - sq_m; -sq_r is row-constant, rank-invariant)
        char* ssc = smraw + KS_B + (size_t)cur * KTILE;
        const float* sqc = sqmF + cur * 128;
        #pragma unroll
        for (int mi = 0; mi < 4; ++mi) {
            int r0 = wm * 64 + mi * 16 + g;
            #pragma unroll
            for (int ni = 0; ni < 4; ++ni) {
                int C = wn * 32 + ni * 8 + t * 2;
                float2 sm2 = *(const float2*)&sqc[C];
                float* a = acc[mi][ni];
                *(float2*)(ssc + r0 * KROWB + C * 4) =
                    make_float2(fmaf(2.f, a[0], -sm2.x), fmaf(2.f, a[1], -sm2.y));
                *(float2*)(ssc + (r0 + 8) * KROWB + C * 4) =
                    make_float2(fmaf(2.f, a[2], -sm2.x), fmaf(2.f, a[3], -sm2.y));
            }
        }
        __syncthreads();

        // top-9: each thread scans 64 cols of its fixed row, float-threshold gated
        const char* srow = ssc + rB * KROWB + cs * 256;
        #pragma unroll
        for (int j4 = 0; j4 < 16; ++j4) {
            const float4 v = *(const float4*)(srow + j4 * 16);
            float m = fmaxf(fmaxf(v.x, v.y), fmaxf(v.z, v.w));
            if (m >= thr) {   // rare after warm-up; >= keeps exact tie handling
                float vv[4] = {v.x, v.y, v.z, v.w};
                #pragma unroll
                for (int q = 0; q < 4; ++q)
                    if (vv[q] >= thr)
                        tkInsert(tk, packKey(vv[q], (unsigned)(m0 + cs * 64 + j4 * 4 + q)));
                thr = unpackVal(tk[8]);
            }
        }
    }

    // merge the two col-slices of each row (partner thread tid^1), write keys
    for (int k = 0; k < KNB; ++k) {
        unsigned long long m = tk[0];
        unsigned long long o = __shfl_xor_sync(0xffffffffu, m, 1, 2);
        if (o > m) m = o;
        if (tk[0] == m) {    // keys unique: exactly one of the pair pops
            #pragma unroll
            for (int i = 0; i < 8; ++i) tk[i] = tk[i + 1];
            tk[8] = 0ull;
        }
        if (cs == 0)
            g_nnk[((size_t)(b * 2 + half) * NPTS + n0 + rB) * KNB + k] = m;
    }
}

// ---------------- merge the two column-halves' top-9 lists ----------------
__global__ void nnmerge_kernel() {
    int i = blockIdx.x * 256 + threadIdx.x;
    if (i >= BB * NPTS) return;
    int b = i >> 12, row = i & (NPTS - 1);
    const unsigned long long* k0 = g_nnk + ((size_t)(b * 2 + 0) * NPTS + row) * KNB;
    const unsigned long long* k1 = g_nnk + ((size_t)(b * 2 + 1) * NPTS + row) * KNB;
    unsigned long long tk[9];
    #pragma unroll
    for (int k = 0; k < KNB; ++k) tk[k] = k0[k];
    #pragma unroll
    for (int k = 0; k < KNB; ++k) tkInsert(tk, k1[k]);
    #pragma unroll
    for (int k = 0; k < KNB; ++k)
        g_nn[(b * NPTS + row) * KNB + k] = (int)(0xFFFFFFFFu - (unsigned)tk[k]);
}

// ================= p/q GEMM (round-7 proven): y[b][n][o] = (wct[o].xn[n])*nrm[n] =================
#define KM   64
#define KN   128
#define KSTR 264

__device__ __forceinline__ void gmma_block(float acc[2][4][4], uint32_t aAddr, uint32_t bAddr) {
    #pragma unroll
    for (int seg = 0; seg < 3; ++seg) {
        const int aoff = (seg == 2) ? 256 : 0;
        const int boff = (seg == 1) ? 256 : 0;
        #pragma unroll
        for (int kk = 0; kk < 8; ++kk) {
            uint32_t a[2][4], bq[2][4];
            ldsm4(a[0], aAddr + aoff + kk * 32);
            ldsm4(a[1], aAddr + 16 * KROWB + aoff + kk * 32);
            ldsm4(bq[0], bAddr + boff + kk * 32);
            ldsm4(bq[1], bAddr + 16 * KROWB + boff + kk * 32);
            #pragma unroll
            for (int mi = 0; mi < 2; ++mi) {
                mma_bf16(acc[mi][0], a[mi][0], a[mi][1], a[mi][2], a[mi][3], bq[0][0], bq[0][1]);
                mma_bf16(acc[mi][1], a[mi][0], a[mi][1], a[mi][2], a[mi][3], bq[0][2], bq[0][3]);
                mma_bf16(acc[mi][2], a[mi][0], a[mi][1], a[mi][2], a[mi][3], bq[1][0], bq[1][1]);
                mma_bf16(acc[mi][3], a[mi][0], a[mi][1], a[mi][2], a[mi][3], bq[1][2], bq[1][3]);
            }
        }
    }
}
__device__ __forceinline__ void gemm_issueW(int o0, uint32_t bsAddr, int tid) {
    const uint4* wbG = (const uint4*)g_wb;
    #pragma unroll 4
    for (int i = tid; i < KN * 32; i += 256) {
        int r = i >> 5, j = i & 31;
        cp16(bsAddr + (unsigned)(r * 33 + j) * 16, wbG + (size_t)(o0 + r) * 32 + j);
    }
    CP_COMMIT();
}

__global__ void __launch_bounds__(256, 1)
gemm_kernel() {
    extern __shared__ char smraw[];
    __nv_bfloat16* As  = (__nv_bfloat16*)smraw;       // [64][264]  (points)
    __nv_bfloat16* Bs0 = As + KM * KSTR;              // 2 x [128][264] (wct)
    float* nrmr = (float*)(Bs0 + 2 * KN * KSTR);      // [64]

    const int tid = threadIdx.x;
    const int b   = blockIdx.y;
    const int n0  = blockIdx.x * KM;
    const uint4* __restrict__ abG = (const uint4*)g_ab;

    const uint32_t asAddr  = (uint32_t)__cvta_generic_to_shared(As);
    const uint32_t bsAddr0 = (uint32_t)__cvta_generic_to_shared(Bs0);
    gemm_issueW(0, bsAddr0, tid);

    for (int i = tid; i < KM * 32; i += 256) {
        int r = i >> 5, j = i & 31;
        ((uint4*)As)[r * 33 + j] = abG[(size_t)(b * NPTS + n0 + r) * 32 + j];
    }
    if (tid < KM) nrmr[tid] = g_nrm[b * NPTS + n0 + tid];

    const int wid = tid >> 5, l = tid & 31;
    const int wm = wid & 1, wn = wid >> 1;
    const int g = l >> 2, t = l & 3;

    const uint32_t aFrag = asAddr + (unsigned)(wm * 32 + (l & 15)) * KROWB + (unsigned)(l >> 4) * 16;
    const uint32_t bFragOff = (unsigned)(wn * 32 + (l >> 4) * 8 + (l & 7)) * KROWB
                            + (unsigned)((l >> 3) & 1) * 16;

    float* yb = g_y + (size_t)b * NPTS * OC2;

    for (int chunk = 0; chunk < OC2 / KN; ++chunk) {
        const int cur = chunk & 1;
        CP_WAIT0();
        __syncthreads();
        if (chunk + 1 < OC2 / KN)
            gemm_issueW((chunk + 1) * KN, bsAddr0 + (unsigned)(1 - cur) * KN * KSTR * 2, tid);

        float acc[2][4][4];
        #pragma unroll
        for (int mi = 0; mi < 2; ++mi)
            #pragma unroll
            for (int ni = 0; ni < 4; ++ni)
                #pragma unroll
                for (int q = 0; q < 4; ++q) acc[mi][ni][q] = 0.f;

        gmma_block(acc, aFrag, bsAddr0 + (unsigned)cur * KN * KSTR * 2 + bFragOff);

        const int oc = chunk * KN;
        #pragma unroll
        for (int mi = 0; mi < 2; ++mi) {
            int r = wm * 32 + mi * 16 + g;
            float nr0 = nrmr[r], nr1 = nrmr[r + 8];
            #pragma unroll
            for (int ni = 0; ni < 4; ++ni) {
                int c = wn * 32 + ni * 8 + t * 2;
                float* a = acc[mi][ni];
                *(float2*)&yb[(size_t)(n0 + r) * OC2 + oc + c] =
                    make_float2(a[0] * nr0, a[1] * nr0);
                *(float2*)&yb[(size_t)(n0 + r + 8) * OC2 + oc + c] =
                    make_float2(a[2] * nr1, a[3] * nr1);
            }
        }
        __syncthreads();
    }
}

// ---------------- epilogue: gather + max + relu ----------------
__global__ void final_kernel(const float* __restrict__ bias, float* __restrict__ out) {
    __shared__ int sj[KNB];
    const int n = blockIdx.x;
    const int b = blockIdx.y;
    const int o = threadIdx.x;
    if (o < KNB) sj[o] = g_nn[(b * NPTS + n) * KNB + o];
    __syncthreads();
    const float* yb = g_y + (size_t)b * NPTS * OC2;
    float p = yb[(size_t)n * OC2 + o];
    float best = -3.4e38f;
    #pragma unroll
    for (int k = 0; k < KNB; ++k)
        best = fmaxf(best, yb[(size_t)sj[k] * OC2 + OC + o]);
    float v = fmaxf(p + best + bias[o], 0.f);
    out[((size_t)b * OC + o) * NPTS + n] = v;
}

// ---------------- launch ----------------
extern "C" void kernel_launch(void* const* d_in, const int* in_sizes, int n_in,
                              void* d_out, int out_size) {
    const float* x    = (const float*)d_in[0];
    const float* w    = (const float*)d_in[1];
    const float* bias = (const float*)d_in[2];
    float* out = (float*)d_out;

    const int prep_smem = (128 * 129 + 128) * (int)sizeof(float);       // 66560
    const int gemm_smem = KM*KSTR*2 + 2*KN*KSTR*2 + KM * 4;             // 169216
    cudaFuncSetAttribute(prep_kernel, cudaFuncAttributeMaxDynamicSharedMemorySize, prep_smem);
    cudaFuncSetAttribute(knn_kernel,  cudaFuncAttributeMaxDynamicSharedMemorySize, KNN_SMEM);
    cudaFuncSetAttribute(gemm_kernel, cudaFuncAttributeMaxDynamicSharedMemorySize, gemm_smem);

    prep_kernel   <<<dim3(NPTS / 128, BB), 128, prep_smem>>>(x);
    wprep_kernel  <<<(OC2 * CCH + 255) / 256, 256>>>(w);
    gemm_kernel   <<<dim3(NPTS / KM, BB), 256, gemm_smem>>>();
    knn_kernel    <<<dim3(NPTS / 128, 2, BB), 256, KNN_SMEM>>>();
    nnmerge_kernel<<<(BB * NPTS + 255) / 256, 256>>>();
    final_kernel  <<<dim3(NPTS, BB), 256>>>(bias, out);
}

// round 15
// speedup vs baseline: 1.3547x; 1.1460x over previous
#include <cuda_runtime.h>
#include <cuda_bf16.h>
#include <cstdint>

#define NPTS 4096
#define CCH  128
#define BB   2
#define KNB  9
#define OC   256
#define OC2  512

// -------- scratch (no allocation allowed) --------
__device__ __nv_bfloat16 g_ab[(size_t)BB*NPTS*256];  // per point: [hi(128) | lo(128)] of normalized x
__device__ __nv_bfloat16 g_wb[(size_t)OC2*256];      // per out-channel: [hi(128) | lo(128)] of wct
__device__ float g_sq[BB*NPTS];                      // squared norms of normalized pts
__device__ float g_nrm[BB*NPTS];                     // scale s*inv (~||x||)
__device__ float g_y[(size_t)BB*NPTS*OC2];           // (B,N,512): [0:256]=p, [256:512]=q
__device__ int   g_nn[BB*NPTS*KNB];                  // knn indices
__device__ unsigned long long g_nnk[(size_t)BB*2*NPTS*KNB]; // per-half top-9 keys

#define CP_COMMIT() asm volatile("cp.async.commit_group;" ::: "memory")
#define CP_WAIT0()  asm volatile("cp.async.wait_group 0;" ::: "memory")
__device__ __forceinline__ void cp16(uint32_t dst, const void* src) {
    asm volatile("cp.async.cg.shared.global [%0], [%1], 16;" :: "r"(dst), "l"(src) : "memory");
}

// ---------------- prep: normalize, split to bf16 hi/lo (transposed), sq, nrm ----------------
__global__ void __launch_bounds__(128) prep_kernel(const float* __restrict__ x) {
    extern __shared__ float psm[];
    float* sm   = psm;            // [128][129]
    float* invs = psm + 128*129;  // [128]
    const int b = blockIdx.y, n0 = blockIdx.x * 128, tid = threadIdx.x;
    const float* xb = x + (size_t)b * CCH * NPTS;

    for (int i = tid; i < 128 * 128; i += 128) {
        int c = i >> 7, n = i & 127;
        sm[c * 129 + n] = xb[c * NPTS + n0 + n];
    }
    __syncthreads();

    float s = 0.f;
    #pragma unroll 8
    for (int c = 0; c < 128; ++c) { float v = sm[c * 129 + tid]; s = fmaf(v, v, s); }
    float inv = rsqrtf(s + 1e-12f);
    g_sq[b * NPTS + n0 + tid]  = s * inv * inv;
    g_nrm[b * NPTS + n0 + tid] = s * inv;
    invs[tid] = inv;
    __syncthreads();

    const int wid = tid >> 5, l = tid & 31;
    for (int p = wid; p < 128; p += 4) {
        float ip = invs[p];
        __nv_bfloat16 hi[4], lo[4];
        #pragma unroll
        for (int q = 0; q < 4; ++q) {
            float v = sm[(4 * l + q) * 129 + p] * ip;
            hi[q] = __float2bfloat16(v);
            lo[q] = __float2bfloat16(v - __bfloat162float(hi[q]));
        }
        __nv_bfloat16* dst = g_ab + (size_t)(b * NPTS + n0 + p) * 256;
        *(uint2*)(dst + 4 * l)       = *(uint2*)hi;
        *(uint2*)(dst + 128 + 4 * l) = *(uint2*)lo;
    }
}

// ---------------- prep: combined weight, bf16 hi/lo, layout [o][hi128|lo128] ----------------
__global__ void wprep_kernel(const float* __restrict__ w) {
    int i = blockIdx.x * 256 + threadIdx.x;
    if (i >= OC2 * CCH) return;
    int o = i >> 7, c = i & 127;
    float v;
    if (o < OC) v = w[o * 256 + c] - w[o * 256 + 128 + c];   // w1 - w2
    else        v = w[(o - OC) * 256 + 128 + c];             // w2
    __nv_bfloat16 hi = __float2bfloat16(v);
    __nv_bfloat16 lo = __float2bfloat16(v - __bfloat162float(hi));
    g_wb[(size_t)o * 256 + c]       = hi;
    g_wb[(size_t)o * 256 + 128 + c] = lo;
}

// ---------------- shared helpers ----------------
__device__ __forceinline__ unsigned long long packKey(float v, unsigned idx) {
    unsigned u = __float_as_uint(v);
    u = (u & 0x80000000u) ? ~u : (u | 0x80000000u);   // order-preserving float->uint
    return ((unsigned long long)u << 32) | (0xFFFFFFFFu - idx);
}
__device__ __forceinline__ void tkInsert(unsigned long long* tk, unsigned long long key) {
    if (key > tk[8]) {
        #pragma unroll
        for (int i = 0; i < 9; ++i) {
            unsigned long long a = tk[i];
            bool g = key > a;
            tk[i] = g ? key : a;
            key   = g ? a : key;
        }
    }
}
__device__ __forceinline__ void mma_bf16(float* c,
        uint32_t a0, uint32_t a1, uint32_t a2, uint32_t a3,
        uint32_t b0, uint32_t b1) {
    asm volatile(
        "mma.sync.aligned.m16n8k16.row.col.f32.bf16.bf16.f32 "
        "{%0,%1,%2,%3},{%4,%5,%6,%7},{%8,%9},{%0,%1,%2,%3};"
        : "+f"(c[0]), "+f"(c[1]), "+f"(c[2]), "+f"(c[3])
        : "r"(a0), "r"(a1), "r"(a2), "r"(a3), "r"(b0), "r"(b1));
}
__device__ __forceinline__ void ldsm4(uint32_t* r, uint32_t addr) {
    asm volatile("ldmatrix.sync.aligned.m8n8.x4.shared.b16 {%0,%1,%2,%3}, [%4];"
        : "=r"(r[0]), "=r"(r[1]), "=r"(r[2]), "=r"(r[3]) : "r"(addr));
}

// ================= knn: 128x128 CTA tile, padded 528B rows, seg-reuse MMA =================
// smem: A [128 x 528B] @0, B double buffer 2 x [128 x 528B] @67584, sqm 2x128f @202752.
// Ssc overlays B[cur] (128 floats = 512B fit in the 528B row).
#define KROWB 528
#define KTILE 67584            // 128 * 528
#define KS_B   67584
#define KS_SQM 202752
#define KNN_SMEM 203776
#define NCHUNK 16              // 2048 cols per CTA / 128

__device__ __forceinline__ void knn_issueB(int b, int m0, uint32_t bufAddr, uint32_t sqmAddr, int tid) {
    const uint4* abG = (const uint4*)g_ab;
    #pragma unroll 4
    for (int i = tid; i < 128 * 32; i += 256) {
        int r = i >> 5, j = i & 31;
        cp16(bufAddr + (unsigned)(r * 33 + j) * 16, abG + (size_t)(b * NPTS + m0 + r) * 32 + j);
    }
    if (tid < 32)
        cp16(sqmAddr + tid * 16, g_sq + b * NPTS + m0 + tid * 4);
    CP_COMMIT();
}

__global__ void __launch_bounds__(256, 1)
knn_kernel() {
    extern __shared__ char smraw[];
    const uint32_t smem_base = (uint32_t)__cvta_generic_to_shared(smraw);
    const uint32_t asAddr  = smem_base;
    const uint32_t bAddr0  = smem_base + KS_B;
    const uint32_t sqmAddr = smem_base + KS_SQM;
    float* sqmF = (float*)(smraw + KS_SQM);

    const int tid = threadIdx.x, wid = tid >> 5, l = tid & 31;
    const int b = blockIdx.z, half = blockIdx.y, n0 = blockIdx.x * 128;
    const int colBase = half * 2048;

    // prologue: A tile + B chunk0 + sqm0, one cp.async group
    {
        const uint4* abG = (const uint4*)g_ab;
        #pragma unroll 4
        for (int i = tid; i < 128 * 32; i += 256) {
            int r = i >> 5, j = i & 31;
            cp16(asAddr + (unsigned)(r * 33 + j) * 16, abG + (size_t)(b * NPTS + n0 + r) * 32 + j);
        }
    }
    knn_issueB(b, colBase, bAddr0, sqmAddr, tid);

    const int wm = wid & 1, wn = wid >> 1;        // 2x4 warp grid, warp tile 64x32
    const int g = l >> 2, t = l & 3;
    const int rB = tid >> 1, cs = tid & 1;        // topk: 2 threads per row, 64 cols each

    // per-thread ldsm fragment bases (padded layout: plain strides, no swizzle)
    const uint32_t aFrag = asAddr + (unsigned)(wm * 64 + (l & 15)) * KROWB + (unsigned)(l >> 4) * 16;
    const uint32_t bFragOff = (unsigned)(wn * 32 + (l >> 4) * 8 + (l & 7)) * KROWB
                            + (unsigned)((l >> 3) & 1) * 16;

    unsigned long long tk[9];
    #pragma unroll
    for (int i = 0; i < 9; ++i) tk[i] = 0ull;

    for (int chunk = 0; chunk < NCHUNK; ++chunk) {
        const int cur = chunk & 1;
        const int m0  = colBase + chunk * 128;

        CP_WAIT0();          // B[cur] + sqm[cur] resident
        __syncthreads();     // everyone sees it; prev Ssc (in B[1-cur]) reads done

        if (chunk + 1 < NCHUNK)   // next load -> B[1-cur], overlaps MMA+scatter+topk
            knn_issueB(b, m0 + 128, bAddr0 + (unsigned)(1 - cur) * KTILE,
                       sqmAddr + (unsigned)(1 - cur) * 512, tid);

        const uint32_t bFrag = bAddr0 + (unsigned)cur * KTILE + bFragOff;

        float acc[4][4][4];
        #pragma unroll
        for (int mi = 0; mi < 4; ++mi)
            #pragma unroll
            for (int ni = 0; ni < 4; ++ni)
                #pragma unroll
                for (int q = 0; q < 4; ++q) acc[mi][ni][q] = 0.f;

        // emulated-fp32 K=384 with hi/lo fragment REUSE:
        // per kk: load aHi,bHi -> (hi,hi); load bLo -> (hi,lo); load aLo -> (lo,hi)
        // 12 ldsm4 per kk instead of 18 (lo halves live at +256B in the row)
        #pragma unroll
        for (int kk = 0; kk < 8; ++kk) {
            uint32_t aHi[4][4], aLo[4][4], bHi[2][4], bLo[2][4];
            #pragma unroll
            for (int mi = 0; mi < 4; ++mi)
                ldsm4(aHi[mi], aFrag + (unsigned)(mi * 16 * KROWB) + kk * 32);
            ldsm4(bHi[0], bFrag + kk * 32);
            ldsm4(bHi[1], bFrag + 16 * KROWB + kk * 32);
            #pragma unroll
            for (int mi = 0; mi < 4; ++mi) {   // (hi, hi)
                mma_bf16(acc[mi][0], aHi[mi][0], aHi[mi][1], aHi[mi][2], aHi[mi][3], bHi[0][0], bHi[0][1]);
                mma_bf16(acc[mi][1], aHi[mi][0], aHi[mi][1], aHi[mi][2], aHi[mi][3], bHi[0][2], bHi[0][3]);
                mma_bf16(acc[mi][2], aHi[mi][0], aHi[mi][1], aHi[mi][2], aHi[mi][3], bHi[1][0], bHi[1][1]);
                mma_bf16(acc[mi][3], aHi[mi][0], aHi[mi][1], aHi[mi][2], aHi[mi][3], bHi[1][2], bHi[1][3]);
            }
            ldsm4(bLo[0], bFrag + 256 + kk * 32);
            ldsm4(bLo[1], bFrag + 16 * KROWB + 256 + kk * 32);
            #pragma unroll
            for (int mi = 0; mi < 4; ++mi) {   // (hi, lo)
                mma_bf16(acc[mi][0], aHi[mi][0], aHi[mi][1], aHi[mi][2], aHi[mi][3], bLo[0][0], bLo[0][1]);
                mma_bf16(acc[mi][1], aHi[mi][0], aHi[mi][1], aHi[mi][2], aHi[mi][3], bLo[0][2], bLo[0][3]);
                mma_bf16(acc[mi][2], aHi[mi][0], aHi[mi][1], aHi[mi][2], aHi[mi][3], bLo[1][0], bLo[1][1]);
                mma_bf16(acc[mi][3], aHi[mi][0], aHi[mi][1], aHi[mi][2], aHi[mi][3], bLo[1][2], bLo[1][3]);
            }
            #pragma unroll
            for (int mi = 0; mi < 4; ++mi)
                ldsm4(aLo[mi], aFrag + (unsigned)(mi * 16 * KROWB) + 256 + kk * 32);
            #pragma unroll
            for (int mi = 0; mi < 4; ++mi) {   // (lo, hi)
                mma_bf16(acc[mi][0], aLo[mi][0], aLo[mi][1], aLo[mi][2], aLo[mi][3], bHi[0][0], bHi[0][1]);
                mma_bf16(acc[mi][1], aLo[mi][0], aLo[mi][1], aLo[mi][2], aLo[mi][3], bHi[0][2], bHi[0][3]);
                mma_bf16(acc[mi][2], aLo[mi][0], aLo[mi][1], aLo[mi][2], aLo[mi][3], bHi[1][0], bHi[1][1]);
                mma_bf16(acc[mi][3], aLo[mi][0], aLo[mi][1], aLo[mi][2], aLo[mi][3], bHi[1][2], bHi[1][3]);
            }
        }

        __syncthreads();     // all MMA reads of B[cur] done -> Ssc may overlay it

        // scatter rank values (2*inner - sq_m; -sq_r is row-constant, rank-invariant)
        char* ssc = smraw + KS_B + (size_t)cur * KTILE;
        const float* sqc = sqmF + cur * 128;
        #pragma unroll
        for (int mi = 0; mi < 4; ++mi) {
            int r0 = wm * 64 + mi * 16 + g;
            #pragma unroll
            for (int ni = 0; ni < 4; ++ni) {
                int C = wn * 32 + ni * 8 + t * 2;
                float2 sm2 = *(const float2*)&sqc[C];
                float* a = acc[mi][ni];
                *(float2*)(ssc + r0 * KROWB + C * 4) =
                    make_float2(fmaf(2.f, a[0], -sm2.x), fmaf(2.f, a[1], -sm2.y));
                *(float2*)(ssc + (r0 + 8) * KROWB + C * 4) =
                    make_float2(fmaf(2.f, a[2], -sm2.x), fmaf(2.f, a[3], -sm2.y));
            }
        }
        __syncthreads();

        // top-9: each thread scans 64 cols of its fixed row (ungated — r10-proven)
        const char* srow = ssc + rB * KROWB + cs * 256;
        #pragma unroll
        for (int j4 = 0; j4 < 16; ++j4) {
            const float4 v = *(const float4*)(srow + j4 * 16);
            float vv[4] = {v.x, v.y, v.z, v.w};
            #pragma unroll
            for (int q = 0; q < 4; ++q)
                tkInsert(tk, packKey(vv[q], (unsigned)(m0 + cs * 64 + j4 * 4 + q)));
        }
    }

    // merge the two col-slices of each row (partner thread tid^1), write keys
    for (int k = 0; k < KNB; ++k) {
        unsigned long long m = tk[0];
        unsigned long long o = __shfl_xor_sync(0xffffffffu, m, 1, 2);
        if (o > m) m = o;
        if (tk[0] == m) {    // keys unique: exactly one of the pair pops
            #pragma unroll
            for (int i = 0; i < 8; ++i) tk[i] = tk[i + 1];
            tk[8] = 0ull;
        }
        if (cs == 0)
            g_nnk[((size_t)(b * 2 + half) * NPTS + n0 + rB) * KNB + k] = m;
    }
}

// ---------------- merge the two column-halves' top-9 lists ----------------
__global__ void nnmerge_kernel() {
    int i = blockIdx.x * 256 + threadIdx.x;
    if (i >= BB * NPTS) return;
    int b = i >> 12, row = i & (NPTS - 1);
    const unsigned long long* k0 = g_nnk + ((size_t)(b * 2 + 0) * NPTS + row) * KNB;
    const unsigned long long* k1 = g_nnk + ((size_t)(b * 2 + 1) * NPTS + row) * KNB;
    unsigned long long tk[9];
    #pragma unroll
    for (int k = 0; k < KNB; ++k) tk[k] = k0[k];
    #pragma unroll
    for (int k = 0; k < KNB; ++k) tkInsert(tk, k1[k]);
    #pragma unroll
    for (int k = 0; k < KNB; ++k)
        g_nn[(b * NPTS + row) * KNB + k] = (int)(0xFFFFFFFFu - (unsigned)tk[k]);
}

// ================= p/q GEMM (round-7 proven): y[b][n][o] = (wct[o].xn[n])*nrm[n] =================
#define KM   64
#define KN   128
#define KSTR 264

__device__ __forceinline__ void gmma_block(float acc[2][4][4], uint32_t aAddr, uint32_t bAddr) {
    #pragma unroll
    for (int seg = 0; seg < 3; ++seg) {
        const int aoff = (seg == 2) ? 256 : 0;
        const int boff = (seg == 1) ? 256 : 0;
        #pragma unroll
        for (int kk = 0; kk < 8; ++kk) {
            uint32_t a[2][4], bq[2][4];
            ldsm4(a[0], aAddr + aoff + kk * 32);
            ldsm4(a[1], aAddr + 16 * KROWB + aoff + kk * 32);
            ldsm4(bq[0], bAddr + boff + kk * 32);
            ldsm4(bq[1], bAddr + 16 * KROWB + boff + kk * 32);
            #pragma unroll
            for (int mi = 0; mi < 2; ++mi) {
                mma_bf16(acc[mi][0], a[mi][0], a[mi][1], a[mi][2], a[mi][3], bq[0][0], bq[0][1]);
                mma_bf16(acc[mi][1], a[mi][0], a[mi][1], a[mi][2], a[mi][3], bq[0][2], bq[0][3]);
                mma_bf16(acc[mi][2], a[mi][0], a[mi][1], a[mi][2], a[mi][3], bq[1][0], bq[1][1]);
                mma_bf16(acc[mi][3], a[mi][0], a[mi][1], a[mi][2], a[mi][3], bq[1][2], bq[1][3]);
            }
        }
    }
}
__device__ __forceinline__ void gemm_issueW(int o0, uint32_t bsAddr, int tid) {
    const uint4* wbG = (const uint4*)g_wb;
    #pragma unroll 4
    for (int i = tid; i < KN * 32; i += 256) {
        int r = i >> 5, j = i & 31;
        cp16(bsAddr + (unsigned)(r * 33 + j) * 16, wbG + (size_t)(o0 + r) * 32 + j);
    }
    CP_COMMIT();
}

__global__ void __launch_bounds__(256, 1)
gemm_kernel() {
    extern __shared__ char smraw[];
    __nv_bfloat16* As  = (__nv_bfloat16*)smraw;       // [64][264]  (points)
    __nv_bfloat16* Bs0 = As + KM * KSTR;              // 2 x [128][264] (wct)
    float* nrmr = (float*)(Bs0 + 2 * KN * KSTR);      // [64]

    const int tid = threadIdx.x;
    const int b   = blockIdx.y;
    const int n0  = blockIdx.x * KM;
    const uint4* __restrict__ abG = (const uint4*)g_ab;

    const uint32_t asAddr  = (uint32_t)__cvta_generic_to_shared(As);
    const uint32_t bsAddr0 = (uint32_t)__cvta_generic_to_shared(Bs0);
    gemm_issueW(0, bsAddr0, tid);

    for (int i = tid; i < KM * 32; i += 256) {
        int r = i >> 5, j = i & 31;
        ((uint4*)As)[r * 33 + j] = abG[(size_t)(b * NPTS + n0 + r) * 32 + j];
    }
    if (tid < KM) nrmr[tid] = g_nrm[b * NPTS + n0 + tid];

    const int wid = tid >> 5, l = tid & 31;
    const int wm = wid & 1, wn = wid >> 1;
    const int g = l >> 2, t = l & 3;

    const uint32_t aFrag = asAddr + (unsigned)(wm * 32 + (l & 15)) * KROWB + (unsigned)(l >> 4) * 16;
    const uint32_t bFragOff = (unsigned)(wn * 32 + (l >> 4) * 8 + (l & 7)) * KROWB
                            + (unsigned)((l >> 3) & 1) * 16;

    float* yb = g_y + (size_t)b * NPTS * OC2;

    for (int chunk = 0; chunk < OC2 / KN; ++chunk) {
        const int cur = chunk & 1;
        CP_WAIT0();
        __syncthreads();
        if (chunk + 1 < OC2 / KN)
            gemm_issueW((chunk + 1) * KN, bsAddr0 + (unsigned)(1 - cur) * KN * KSTR * 2, tid);

        float acc[2][4][4];
        #pragma unroll
        for (int mi = 0; mi < 2; ++mi)
            #pragma unroll
            for (int ni = 0; ni < 4; ++ni)
                #pragma unroll
                for (int q = 0; q < 4; ++q) acc[mi][ni][q] = 0.f;

        gmma_block(acc, aFrag, bsAddr0 + (unsigned)cur * KN * KSTR * 2 + bFragOff);

        const int oc = chunk * KN;
        #pragma unroll
        for (int mi = 0; mi < 2; ++mi) {
            int r = wm * 32 + mi * 16 + g;
            float nr0 = nrmr[r], nr1 = nrmr[r + 8];
            #pragma unroll
            for (int ni = 0; ni < 4; ++ni) {
                int c = wn * 32 + ni * 8 + t * 2;
                float* a = acc[mi][ni];
                *(float2*)&yb[(size_t)(n0 + r) * OC2 + oc + c] =
                    make_float2(a[0] * nr0, a[1] * nr0);
                *(float2*)&yb[(size_t)(n0 + r + 8) * OC2 + oc + c] =
                    make_float2(a[2] * nr1, a[3] * nr1);
            }
        }
        __syncthreads();
    }
}

// ---------------- epilogue: gather + max + relu ----------------
__global__ void final_kernel(const float* __restrict__ bias, float* __restrict__ out) {
    __shared__ int sj[KNB];
    const int n = blockIdx.x;
    const int b = blockIdx.y;
    const int o = threadIdx.x;
    if (o < KNB) sj[o] = g_nn[(b * NPTS + n) * KNB + o];
    __syncthreads();
    const float* yb = g_y + (size_t)b * NPTS * OC2;
    float p = yb[(size_t)n * OC2 + o];
    float best = -3.4e38f;
    #pragma unroll
    for (int k = 0; k < KNB; ++k)
        best = fmaxf(best, yb[(size_t)sj[k] * OC2 + OC + o]);
    float v = fmaxf(p + best + bias[o], 0.f);
    out[((size_t)b * OC + o) * NPTS + n] = v;
}

// ---------------- launch ----------------
extern "C" void kernel_launch(void* const* d_in, const int* in_sizes, int n_in,
                              void* d_out, int out_size) {
    const float* x    = (const float*)d_in[0];
    const float* w    = (const float*)d_in[1];
    const float* bias = (const float*)d_in[2];
    float* out = (float*)d_out;

    const int prep_smem = (128 * 129 + 128) * (int)sizeof(float);       // 66560
    const int gemm_smem = KM*KSTR*2 + 2*KN*KSTR*2 + KM * 4;             // 169216
    cudaFuncSetAttribute(prep_kernel, cudaFuncAttributeMaxDynamicSharedMemorySize, prep_smem);
    cudaFuncSetAttribute(knn_kernel,  cudaFuncAttributeMaxDynamicSharedMemorySize, KNN_SMEM);
    cudaFuncSetAttribute(gemm_kernel, cudaFuncAttributeMaxDynamicSharedMemorySize, gemm_smem);

    prep_kernel   <<<dim3(NPTS / 128, BB), 128, prep_smem>>>(x);
    wprep_kernel  <<<(OC2 * CCH + 255) / 256, 256>>>(w);
    gemm_kernel   <<<dim3(NPTS / KM, BB), 256, gemm_smem>>>();
    knn_kernel    <<<dim3(NPTS / 128, 2, BB), 256, KNN_SMEM>>>();
    nnmerge_kernel<<<(BB * NPTS + 255) / 256, 256>>>();
    final_kernel  <<<dim3(NPTS, BB), 256>>>(bias, out);
}

// round 16
// speedup vs baseline: 1.5549x; 1.1478x over previous
#include <cuda_runtime.h>
#include <cuda_bf16.h>
#include <cstdint>

#define NPTS 4096
#define CCH  128
#define BB   2
#define KNB  9
#define OC   256
#define OC2  512

// -------- scratch (no allocation allowed) --------
__device__ __nv_bfloat16 g_ab[(size_t)BB*NPTS*256];  // per point: [hi(128) | lo(128)] of normalized x
__device__ __nv_bfloat16 g_wb[(size_t)OC2*256];      // per out-channel: [hi(128) | lo(128)] of wct
__device__ float g_sq[BB*NPTS];                      // squared norms of normalized pts
__device__ float g_nrm[BB*NPTS];                     // scale s*inv (~||x||)
__device__ float g_y[(size_t)BB*NPTS*OC2];           // (B,N,512): [0:256]=p, [256:512]=q
__device__ int   g_nn[BB*NPTS*KNB];                  // knn indices
__device__ unsigned long long g_nnk[(size_t)BB*2*NPTS*KNB]; // per-half top-9 keys

#define CP_COMMIT() asm volatile("cp.async.commit_group;" ::: "memory")
#define CP_WAIT0()  asm volatile("cp.async.wait_group 0;" ::: "memory")
__device__ __forceinline__ void cp16(uint32_t dst, const void* src) {
    asm volatile("cp.async.cg.shared.global [%0], [%1], 16;" :: "r"(dst), "l"(src) : "memory");
}

// ---------------- prep: normalize, split to bf16 hi/lo (transposed), sq, nrm ----------------
__global__ void __launch_bounds__(128) prep_kernel(const float* __restrict__ x) {
    extern __shared__ float psm[];
    float* sm   = psm;            // [128][129]
    float* invs = psm + 128*129;  // [128]
    const int b = blockIdx.y, n0 = blockIdx.x * 128, tid = threadIdx.x;
    const float* xb = x + (size_t)b * CCH * NPTS;

    for (int i = tid; i < 128 * 128; i += 128) {
        int c = i >> 7, n = i & 127;
        sm[c * 129 + n] = xb[c * NPTS + n0 + n];
    }
    __syncthreads();

    float s = 0.f;
    #pragma unroll 8
    for (int c = 0; c < 128; ++c) { float v = sm[c * 129 + tid]; s = fmaf(v, v, s); }
    float inv = rsqrtf(s + 1e-12f);
    g_sq[b * NPTS + n0 + tid]  = s * inv * inv;
    g_nrm[b * NPTS + n0 + tid] = s * inv;
    invs[tid] = inv;
    __syncthreads();

    const int wid = tid >> 5, l = tid & 31;
    for (int p = wid; p < 128; p += 4) {
        float ip = invs[p];
        __nv_bfloat16 hi[4], lo[4];
        #pragma unroll
        for (int q = 0; q < 4; ++q) {
            float v = sm[(4 * l + q) * 129 + p] * ip;
            hi[q] = __float2bfloat16(v);
            lo[q] = __float2bfloat16(v - __bfloat162float(hi[q]));
        }
        __nv_bfloat16* dst = g_ab + (size_t)(b * NPTS + n0 + p) * 256;
        *(uint2*)(dst + 4 * l)       = *(uint2*)hi;
        *(uint2*)(dst + 128 + 4 * l) = *(uint2*)lo;
    }
}

// ---------------- prep: combined weight, bf16 hi/lo, layout [o][hi128|lo128] ----------------
__global__ void wprep_kernel(const float* __restrict__ w) {
    int i = blockIdx.x * 256 + threadIdx.x;
    if (i >= OC2 * CCH) return;
    int o = i >> 7, c = i & 127;
    float v;
    if (o < OC) v = w[o * 256 + c] - w[o * 256 + 128 + c];   // w1 - w2
    else        v = w[(o - OC) * 256 + 128 + c];             // w2
    __nv_bfloat16 hi = __float2bfloat16(v);
    __nv_bfloat16 lo = __float2bfloat16(v - __bfloat162float(hi));
    g_wb[(size_t)o * 256 + c]       = hi;
    g_wb[(size_t)o * 256 + 128 + c] = lo;
}

// ---------------- shared helpers ----------------
__device__ __forceinline__ unsigned long long packKey(float v, unsigned idx) {
    unsigned u = __float_as_uint(v);
    u = (u & 0x80000000u) ? ~u : (u | 0x80000000u);   // order-preserving float->uint
    return ((unsigned long long)u << 32) | (0xFFFFFFFFu - idx);
}
__device__ __forceinline__ void tkInsert(unsigned long long* tk, unsigned long long key) {
    if (key > tk[8]) {
        #pragma unroll
        for (int i = 0; i < 9; ++i) {
            unsigned long long a = tk[i];
            bool g = key > a;
            tk[i] = g ? key : a;
            key   = g ? a : key;
        }
    }
}
__device__ __forceinline__ void mma_bf16(float* c,
        uint32_t a0, uint32_t a1, uint32_t a2, uint32_t a3,
        uint32_t b0, uint32_t b1) {
    asm volatile(
        "mma.sync.aligned.m16n8k16.row.col.f32.bf16.bf16.f32 "
        "{%0,%1,%2,%3},{%4,%5,%6,%7},{%8,%9},{%0,%1,%2,%3};"
        : "+f"(c[0]), "+f"(c[1]), "+f"(c[2]), "+f"(c[3])
        : "r"(a0), "r"(a1), "r"(a2), "r"(a3), "r"(b0), "r"(b1));
}
__device__ __forceinline__ void ldsm4(uint32_t* r, uint32_t addr) {
    asm volatile("ldmatrix.sync.aligned.m8n8.x4.shared.b16 {%0,%1,%2,%3}, [%4];"
        : "=r"(r[0]), "=r"(r[1]), "=r"(r[2]), "=r"(r[3]) : "r"(addr));
}

// ================= knn: 128x128 CTA tile, padded 528B rows, seg-reuse MMA =================
// smem: A [128 x 528B] @0, B double buffer 2 x [128 x 528B] @67584, sqm 2x128f @202752.
// Ssc overlays B[cur] (128 floats = 512B fit in the 528B row).
#define KROWB 528
#define KTILE 67584            // 128 * 528
#define KS_B   67584
#define KS_SQM 202752
#define KNN_SMEM 203776
#define NCHUNK 16              // 2048 cols per CTA / 128

__device__ __forceinline__ void knn_issueB(int b, int m0, uint32_t bufAddr, uint32_t sqmAddr, int tid) {
    const uint4* abG = (const uint4*)g_ab;
    #pragma unroll 4
    for (int i = tid; i < 128 * 32; i += 256) {
        int r = i >> 5, j = i & 31;
        cp16(bufAddr + (unsigned)(r * 33 + j) * 16, abG + (size_t)(b * NPTS + m0 + r) * 32 + j);
    }
    if (tid < 32)
        cp16(sqmAddr + tid * 16, g_sq + b * NPTS + m0 + tid * 4);
    CP_COMMIT();
}

__global__ void __launch_bounds__(256, 1)
knn_kernel() {
    extern __shared__ char smraw[];
    const uint32_t smem_base = (uint32_t)__cvta_generic_to_shared(smraw);
    const uint32_t asAddr  = smem_base;
    const uint32_t bAddr0  = smem_base + KS_B;
    const uint32_t sqmAddr = smem_base + KS_SQM;
    float* sqmF = (float*)(smraw + KS_SQM);

    const int tid = threadIdx.x, wid = tid >> 5, l = tid & 31;
    const int b = blockIdx.z, half = blockIdx.y, n0 = blockIdx.x * 128;
    const int colBase = half * 2048;

    // prologue: A tile + B chunk0 + sqm0, one cp.async group
    {
        const uint4* abG = (const uint4*)g_ab;
        #pragma unroll 4
        for (int i = tid; i < 128 * 32; i += 256) {
            int r = i >> 5, j = i & 31;
            cp16(asAddr + (unsigned)(r * 33 + j) * 16, abG + (size_t)(b * NPTS + n0 + r) * 32 + j);
        }
    }
    knn_issueB(b, colBase, bAddr0, sqmAddr, tid);

    const int wm = wid & 1, wn = wid >> 1;        // 2x4 warp grid, warp tile 64x32
    const int g = l >> 2, t = l & 3;
    const int rB = tid >> 1, cs = tid & 1;        // topk: 2 threads per row, 64 cols each

    // per-thread ldsm fragment bases (padded layout: plain strides, no swizzle)
    const uint32_t aFrag = asAddr + (unsigned)(wm * 64 + (l & 15)) * KROWB + (unsigned)(l >> 4) * 16;
    const uint32_t bFragOff = (unsigned)(wn * 32 + (l >> 4) * 8 + (l & 7)) * KROWB
                            + (unsigned)((l >> 3) & 1) * 16;

    // top-9 as sorted float values + int indices (FSETP/FSEL on fma pipe, int SEL on alu)
    float tv[9];
    int   tix[9];
    #pragma unroll
    for (int i = 0; i < 9; ++i) { tv[i] = -3.402823466e38f; tix[i] = 0x7FFFFFFF; }

    for (int chunk = 0; chunk < NCHUNK; ++chunk) {
        const int cur = chunk & 1;
        const int m0  = colBase + chunk * 128;

        CP_WAIT0();          // B[cur] + sqm[cur] resident
        __syncthreads();     // everyone sees it; prev Ssc (in B[1-cur]) reads done

        if (chunk + 1 < NCHUNK)   // next load -> B[1-cur], overlaps MMA+scatter+topk
            knn_issueB(b, m0 + 128, bAddr0 + (unsigned)(1 - cur) * KTILE,
                       sqmAddr + (unsigned)(1 - cur) * 512, tid);

        const uint32_t bFrag = bAddr0 + (unsigned)cur * KTILE + bFragOff;

        float acc[4][4][4];
        #pragma unroll
        for (int mi = 0; mi < 4; ++mi)
            #pragma unroll
            for (int ni = 0; ni < 4; ++ni)
                #pragma unroll
                for (int q = 0; q < 4; ++q) acc[mi][ni][q] = 0.f;

        // emulated-fp32 K=384 with hi/lo fragment REUSE:
        // per kk: load aHi,bHi -> (hi,hi); load bLo -> (hi,lo); load aLo -> (lo,hi)
        #pragma unroll
        for (int kk = 0; kk < 8; ++kk) {
            uint32_t aHi[4][4], aLo[4][4], bHi[2][4], bLo[2][4];
            #pragma unroll
            for (int mi = 0; mi < 4; ++mi)
                ldsm4(aHi[mi], aFrag + (unsigned)(mi * 16 * KROWB) + kk * 32);
            ldsm4(bHi[0], bFrag + kk * 32);
            ldsm4(bHi[1], bFrag + 16 * KROWB + kk * 32);
            #pragma unroll
            for (int mi = 0; mi < 4; ++mi) {   // (hi, hi)
                mma_bf16(acc[mi][0], aHi[mi][0], aHi[mi][1], aHi[mi][2], aHi[mi][3], bHi[0][0], bHi[0][1]);
                mma_bf16(acc[mi][1], aHi[mi][0], aHi[mi][1], aHi[mi][2], aHi[mi][3], bHi[0][2], bHi[0][3]);
                mma_bf16(acc[mi][2], aHi[mi][0], aHi[mi][1], aHi[mi][2], aHi[mi][3], bHi[1][0], bHi[1][1]);
                mma_bf16(acc[mi][3], aHi[mi][0], aHi[mi][1], aHi[mi][2], aHi[mi][3], bHi[1][2], bHi[1][3]);
            }
            ldsm4(bLo[0], bFrag + 256 + kk * 32);
            ldsm4(bLo[1], bFrag + 16 * KROWB + 256 + kk * 32);
            #pragma unroll
            for (int mi = 0; mi < 4; ++mi) {   // (hi, lo)
                mma_bf16(acc[mi][0], aHi[mi][0], aHi[mi][1], aHi[mi][2], aHi[mi][3], bLo[0][0], bLo[0][1]);
                mma_bf16(acc[mi][1], aHi[mi][0], aHi[mi][1], aHi[mi][2], aHi[mi][3], bLo[0][2], bLo[0][3]);
                mma_bf16(acc[mi][2], aHi[mi][0], aHi[mi][1], aHi[mi][2], aHi[mi][3], bLo[1][0], bLo[1][1]);
                mma_bf16(acc[mi][3], aHi[mi][0], aHi[mi][1], aHi[mi][2], aHi[mi][3], bLo[1][2], bLo[1][3]);
            }
            #pragma unroll
            for (int mi = 0; mi < 4; ++mi)
                ldsm4(aLo[mi], aFrag + (unsigned)(mi * 16 * KROWB) + 256 + kk * 32);
            #pragma unroll
            for (int mi = 0; mi < 4; ++mi) {   // (lo, hi)
                mma_bf16(acc[mi][0], aLo[mi][0], aLo[mi][1], aLo[mi][2], aLo[mi][3], bHi[0][0], bHi[0][1]);
                mma_bf16(acc[mi][1], aLo[mi][0], aLo[mi][1], aLo[mi][2], aLo[mi][3], bHi[0][2], bHi[0][3]);
                mma_bf16(acc[mi][2], aLo[mi][0], aLo[mi][1], aLo[mi][2], aLo[mi][3], bHi[1][0], bHi[1][1]);
                mma_bf16(acc[mi][3], aLo[mi][0], aLo[mi][1], aLo[mi][2], aLo[mi][3], bHi[1][2], bHi[1][3]);
            }
        }

        __syncthreads();     // all MMA reads of B[cur] done -> Ssc may overlay it

        // scatter rank values (2*inner - sq_m; -sq_r is row-constant, rank-invariant)
        char* ssc = smraw + KS_B + (size_t)cur * KTILE;
        const float* sqc = sqmF + cur * 128;
        #pragma unroll
        for (int mi = 0; mi < 4; ++mi) {
            int r0 = wm * 64 + mi * 16 + g;
            #pragma unroll
            for (int ni = 0; ni < 4; ++ni) {
                int C = wn * 32 + ni * 8 + t * 2;
                float2 sm2 = *(const float2*)&sqc[C];
                float* a = acc[mi][ni];
                *(float2*)(ssc + r0 * KROWB + C * 4) =
                    make_float2(fmaf(2.f, a[0], -sm2.x), fmaf(2.f, a[1], -sm2.y));
                *(float2*)(ssc + (r0 + 8) * KROWB + C * 4) =
                    make_float2(fmaf(2.f, a[2], -sm2.x), fmaf(2.f, a[3], -sm2.y));
            }
        }
        __syncthreads();

        // top-9: float/idx sorted insert. Strict '>' keeps first-seen (= lowest idx) on ties,
        // matching the packKey ordering exactly (scan order is ascending idx per thread).
        const char* srow = ssc + rB * KROWB + cs * 256;
        #pragma unroll
        for (int j4 = 0; j4 < 16; ++j4) {
            const float4 v = *(const float4*)(srow + j4 * 16);
            float m4 = fmaxf(fmaxf(v.x, v.y), fmaxf(v.z, v.w));
            if (m4 > tv[8]) {
                float vv[4] = {v.x, v.y, v.z, v.w};
                #pragma unroll
                for (int q = 0; q < 4; ++q) {
                    float cv = vv[q];
                    if (cv > tv[8]) {
                        int ci = m0 + cs * 64 + j4 * 4 + q;
                        #pragma unroll
                        for (int i = 0; i < 9; ++i) {
                            bool gg = cv > tv[i];
                            float nv = gg ? cv : tv[i];
                            int   nx = gg ? ci : tix[i];
                            cv = gg ? tv[i] : cv;
                            ci = gg ? tix[i] : ci;
                            tv[i] = nv; tix[i] = nx;
                        }
                    }
                }
            }
        }
    }

    // build u64 keys (value-major, ~idx tiebreak) and merge the two col-slices of each row
    unsigned long long tk[9];
    #pragma unroll
    for (int k = 0; k < KNB; ++k) tk[k] = packKey(tv[k], (unsigned)tix[k]);

    for (int k = 0; k < KNB; ++k) {
        unsigned long long m = tk[0];
        unsigned long long o = __shfl_xor_sync(0xffffffffu, m, 1, 2);
        if (o > m) m = o;
        if (tk[0] == m) {    // keys unique: exactly one of the pair pops
            #pragma unroll
            for (int i = 0; i < 8; ++i) tk[i] = tk[i + 1];
            tk[8] = 0ull;
        }
        if (cs == 0)
            g_nnk[((size_t)(b * 2 + half) * NPTS + n0 + rB) * KNB + k] = m;
    }
}

// ---------------- merge the two column-halves' top-9 lists ----------------
__global__ void nnmerge_kernel() {
    int i = blockIdx.x * 256 + threadIdx.x;
    if (i >= BB * NPTS) return;
    int b = i >> 12, row = i & (NPTS - 1);
    const unsigned long long* k0 = g_nnk + ((size_t)(b * 2 + 0) * NPTS + row) * KNB;
    const unsigned long long* k1 = g_nnk + ((size_t)(b * 2 + 1) * NPTS + row) * KNB;
    unsigned long long tk[9];
    #pragma unroll
    for (int k = 0; k < KNB; ++k) tk[k] = k0[k];
    #pragma unroll
    for (int k = 0; k < KNB; ++k) tkInsert(tk, k1[k]);
    #pragma unroll
    for (int k = 0; k < KNB; ++k)
        g_nn[(b * NPTS + row) * KNB + k] = (int)(0xFFFFFFFFu - (unsigned)tk[k]);
}

// ================= p/q GEMM (round-7 proven): y[b][n][o] = (wct[o].xn[n])*nrm[n] =================
#define KM   64
#define KN   128
#define KSTR 264

__device__ __forceinline__ void gmma_block(float acc[2][4][4], uint32_t aAddr, uint32_t bAddr) {
    #pragma unroll
    for (int seg = 0; seg < 3; ++seg) {
        const int aoff = (seg == 2) ? 256 : 0;
        const int boff = (seg == 1) ? 256 : 0;
        #pragma unroll
        for (int kk = 0; kk < 8; ++kk) {
            uint32_t a[2][4], bq[2][4];
            ldsm4(a[0], aAddr + aoff + kk * 32);
            ldsm4(a[1], aAddr + 16 * KROWB + aoff + kk * 32);
            ldsm4(bq[0], bAddr + boff + kk * 32);
            ldsm4(bq[1], bAddr + 16 * KROWB + boff + kk * 32);
            #pragma unroll
            for (int mi = 0; mi < 2; ++mi) {
                mma_bf16(acc[mi][0], a[mi][0], a[mi][1], a[mi][2], a[mi][3], bq[0][0], bq[0][1]);
                mma_bf16(acc[mi][1], a[mi][0], a[mi][1], a[mi][2], a[mi][3], bq[0][2], bq[0][3]);
                mma_bf16(acc[mi][2], a[mi][0], a[mi][1], a[mi][2], a[mi][3], bq[1][0], bq[1][1]);
                mma_bf16(acc[mi][3], a[mi][0], a[mi][1], a[mi][2], a[mi][3], bq[1][2], bq[1][3]);
            }
        }
    }
}
__device__ __forceinline__ void gemm_issueW(int o0, uint32_t bsAddr, int tid) {
    const uint4* wbG = (const uint4*)g_wb;
    #pragma unroll 4
    for (int i = tid; i < KN * 32; i += 256) {
        int r = i >> 5, j = i & 31;
        cp16(bsAddr + (unsigned)(r * 33 + j) * 16, wbG + (size_t)(o0 + r) * 32 + j);
    }
    CP_COMMIT();
}

__global__ void __launch_bounds__(256, 1)
gemm_kernel() {
    extern __shared__ char smraw[];
    __nv_bfloat16* As  = (__nv_bfloat16*)smraw;       // [64][264]  (points)
    __nv_bfloat16* Bs0 = As + KM * KSTR;              // 2 x [128][264] (wct)
    float* nrmr = (float*)(Bs0 + 2 * KN * KSTR);      // [64]

    const int tid = threadIdx.x;
    const int b   = blockIdx.y;
    const int n0  = blockIdx.x * KM;
    const uint4* __restrict__ abG = (const uint4*)g_ab;

    const uint32_t asAddr  = (uint32_t)__cvta_generic_to_shared(As);
    const uint32_t bsAddr0 = (uint32_t)__cvta_generic_to_shared(Bs0);
    gemm_issueW(0, bsAddr0, tid);

    for (int i = tid; i < KM * 32; i += 256) {
        int r = i >> 5, j = i & 31;
        ((uint4*)As)[r * 33 + j] = abG[(size_t)(b * NPTS + n0 + r) * 32 + j];
    }
    if (tid < KM) nrmr[tid] = g_nrm[b * NPTS + n0 + tid];

    const int wid = tid >> 5, l = tid & 31;
    const int wm = wid & 1, wn = wid >> 1;
    const int g = l >> 2, t = l & 3;

    const uint32_t aFrag = asAddr + (unsigned)(wm * 32 + (l & 15)) * KROWB + (unsigned)(l >> 4) * 16;
    const uint32_t bFragOff = (unsigned)(wn * 32 + (l >> 4) * 8 + (l & 7)) * KROWB
                            + (unsigned)((l >> 3) & 1) * 16;

    float* yb = g_y + (size_t)b * NPTS * OC2;

    for (int chunk = 0; chunk < OC2 / KN; ++chunk) {
        const int cur = chunk & 1;
        CP_WAIT0();
        __syncthreads();
        if (chunk + 1 < OC2 / KN)
            gemm_issueW((chunk + 1) * KN, bsAddr0 + (unsigned)(1 - cur) * KN * KSTR * 2, tid);

        float acc[2][4][4];
        #pragma unroll
        for (int mi = 0; mi < 2; ++mi)
            #pragma unroll
            for (int ni = 0; ni < 4; ++ni)
                #pragma unroll
                for (int q = 0; q < 4; ++q) acc[mi][ni][q] = 0.f;

        gmma_block(acc, aFrag, bsAddr0 + (unsigned)cur * KN * KSTR * 2 + bFragOff);

        const int oc = chunk * KN;
        #pragma unroll
        for (int mi = 0; mi < 2; ++mi) {
            int r = wm * 32 + mi * 16 + g;
            float nr0 = nrmr[r], nr1 = nrmr[r + 8];
            #pragma unroll
            for (int ni = 0; ni < 4; ++ni) {
                int c = wn * 32 + ni * 8 + t * 2;
                float* a = acc[mi][ni];
                *(float2*)&yb[(size_t)(n0 + r) * OC2 + oc + c] =
                    make_float2(a[0] * nr0, a[1] * nr0);
                *(float2*)&yb[(size_t)(n0 + r + 8) * OC2 + oc + c] =
                    make_float2(a[2] * nr1, a[3] * nr1);
            }
        }
        __syncthreads();
    }
}

// ---------------- epilogue: gather + max + relu ----------------
__global__ void final_kernel(const float* __restrict__ bias, float* __restrict__ out) {
    __shared__ int sj[KNB];
    const int n = blockIdx.x;
    const int b = blockIdx.y;
    const int o = threadIdx.x;
    if (o < KNB) sj[o] = g_nn[(b * NPTS + n) * KNB + o];
    __syncthreads();
    const float* yb = g_y + (size_t)b * NPTS * OC2;
    float p = yb[(size_t)n * OC2 + o];
    float best = -3.4e38f;
    #pragma unroll
    for (int k = 0; k < KNB; ++k)
        best = fmaxf(best, yb[(size_t)sj[k] * OC2 + OC + o]);
    float v = fmaxf(p + best + bias[o], 0.f);
    out[((size_t)b * OC + o) * NPTS + n] = v;
}

// ---------------- launch ----------------
extern "C" void kernel_launch(void* const* d_in, const int* in_sizes, int n_in,
                              void* d_out, int out_size) {
    const float* x    = (const float*)d_in[0];
    const float* w    = (const float*)d_in[1];
    const float* bias = (const float*)d_in[2];
    float* out = (float*)d_out;

    const int prep_smem = (128 * 129 + 128) * (int)sizeof(float);       // 66560
    const int gemm_smem = KM*KSTR*2 + 2*KN*KSTR*2 + KM * 4;             // 169216
    cudaFuncSetAttribute(prep_kernel, cudaFuncAttributeMaxDynamicSharedMemorySize, prep_smem);
    cudaFuncSetAttribute(knn_kernel,  cudaFuncAttributeMaxDynamicSharedMemorySize, KNN_SMEM);
    cudaFuncSetAttribute(gemm_kernel, cudaFuncAttributeMaxDynamicSharedMemorySize, gemm_smem);

    prep_kernel   <<<dim3(NPTS / 128, BB), 128, prep_smem>>>(x);
    wprep_kernel  <<<(OC2 * CCH + 255) / 256, 256>>>(w);
    gemm_kernel   <<<dim3(NPTS / KM, BB), 256, gemm_smem>>>();
    knn_kernel    <<<dim3(NPTS / 128, 2, BB), 256, KNN_SMEM>>>();
    nnmerge_kernel<<<(BB * NPTS + 255) / 256, 256>>>();
    final_kernel  <<<dim3(NPTS, BB), 256>>>(bias, out);
}

// round 17
// speedup vs baseline: 1.6395x; 1.0544x over previous
#include <cuda_runtime.h>
#include <cuda_bf16.h>
#include <cstdint>

#define NPTS 4096
#define CCH  128
#define BB   2
#define KNB  9
#define OC   256
#define OC2  512

// -------- scratch (no allocation allowed) --------
__device__ __nv_bfloat16 g_ab[(size_t)BB*NPTS*256];  // per point: [hi(128) | lo(128)] of normalized x
__device__ __nv_bfloat16 g_wb[(size_t)OC2*256];      // per out-channel: [hi(128) | lo(128)] of wct
__device__ float g_sq[BB*NPTS];                      // squared norms of normalized pts
__device__ float g_nrm[BB*NPTS];                     // scale s*inv (~||x||)
__device__ float g_y[(size_t)BB*NPTS*OC2];           // (B,N,512): [0:256]=p, [256:512]=q
__device__ int   g_nn[BB*NPTS*KNB];                  // knn indices
__device__ unsigned long long g_nnk[(size_t)BB*2*NPTS*KNB]; // per-half top-9 keys

#define CP_COMMIT() asm volatile("cp.async.commit_group;" ::: "memory")
#define CP_WAIT0()  asm volatile("cp.async.wait_group 0;" ::: "memory")
__device__ __forceinline__ void cp16(uint32_t dst, const void* src) {
    asm volatile("cp.async.cg.shared.global [%0], [%1], 16;" :: "r"(dst), "l"(src) : "memory");
}

// ---------------- prep: normalize, split to bf16 hi/lo (transposed), sq, nrm ----------------
__global__ void __launch_bounds__(128) prep_kernel(const float* __restrict__ x) {
    extern __shared__ float psm[];
    float* sm   = psm;            // [128][129]
    float* invs = psm + 128*129;  // [128]
    const int b = blockIdx.y, n0 = blockIdx.x * 128, tid = threadIdx.x;
    const float* xb = x + (size_t)b * CCH * NPTS;

    for (int i = tid; i < 128 * 128; i += 128) {
        int c = i >> 7, n = i & 127;
        sm[c * 129 + n] = xb[c * NPTS + n0 + n];
    }
    __syncthreads();

    float s = 0.f;
    #pragma unroll 8
    for (int c = 0; c < 128; ++c) { float v = sm[c * 129 + tid]; s = fmaf(v, v, s); }
    float inv = rsqrtf(s + 1e-12f);
    g_sq[b * NPTS + n0 + tid]  = s * inv * inv;
    g_nrm[b * NPTS + n0 + tid] = s * inv;
    invs[tid] = inv;
    __syncthreads();

    const int wid = tid >> 5, l = tid & 31;
    for (int p = wid; p < 128; p += 4) {
        float ip = invs[p];
        __nv_bfloat16 hi[4], lo[4];
        #pragma unroll
        for (int q = 0; q < 4; ++q) {
            float v = sm[(4 * l + q) * 129 + p] * ip;
            hi[q] = __float2bfloat16(v);
            lo[q] = __float2bfloat16(v - __bfloat162float(hi[q]));
        }
        __nv_bfloat16* dst = g_ab + (size_t)(b * NPTS + n0 + p) * 256;
        *(uint2*)(dst + 4 * l)       = *(uint2*)hi;
        *(uint2*)(dst + 128 + 4 * l) = *(uint2*)lo;
    }
}

// ---------------- prep: combined weight, bf16 hi/lo, layout [o][hi128|lo128] ----------------
__global__ void wprep_kernel(const float* __restrict__ w) {
    int i = blockIdx.x * 256 + threadIdx.x;
    if (i >= OC2 * CCH) return;
    int o = i >> 7, c = i & 127;
    float v;
    if (o < OC) v = w[o * 256 + c] - w[o * 256 + 128 + c];   // w1 - w2
    else        v = w[(o - OC) * 256 + 128 + c];             // w2
    __nv_bfloat16 hi = __float2bfloat16(v);
    __nv_bfloat16 lo = __float2bfloat16(v - __bfloat162float(hi));
    g_wb[(size_t)o * 256 + c]       = hi;
    g_wb[(size_t)o * 256 + 128 + c] = lo;
}

// ---------------- shared helpers ----------------
__device__ __forceinline__ unsigned long long packKey(float v, unsigned idx) {
    unsigned u = __float_as_uint(v);
    u = (u & 0x80000000u) ? ~u : (u | 0x80000000u);   // order-preserving float->uint
    return ((unsigned long long)u << 32) | (0xFFFFFFFFu - idx);
}
__device__ __forceinline__ void tkInsert(unsigned long long* tk, unsigned long long key) {
    if (key > tk[8]) {
        #pragma unroll
        for (int i = 0; i < 9; ++i) {
            unsigned long long a = tk[i];
            bool g = key > a;
            tk[i] = g ? key : a;
            key   = g ? a : key;
        }
    }
}
__device__ __forceinline__ void mma_bf16(float* c,
        uint32_t a0, uint32_t a1, uint32_t a2, uint32_t a3,
        uint32_t b0, uint32_t b1) {
    asm volatile(
        "mma.sync.aligned.m16n8k16.row.col.f32.bf16.bf16.f32 "
        "{%0,%1,%2,%3},{%4,%5,%6,%7},{%8,%9},{%0,%1,%2,%3};"
        : "+f"(c[0]), "+f"(c[1]), "+f"(c[2]), "+f"(c[3])
        : "r"(a0), "r"(a1), "r"(a2), "r"(a3), "r"(b0), "r"(b1));
}
__device__ __forceinline__ void ldsm4(uint32_t* r, uint32_t addr) {
    asm volatile("ldmatrix.sync.aligned.m8n8.x4.shared.b16 {%0,%1,%2,%3}, [%4];"
        : "=r"(r[0]), "=r"(r[1]), "=r"(r[2]), "=r"(r[3]) : "r"(addr));
}

// ================= knn: 128x128 CTA tile, 512 threads, padded 528B rows =================
// smem: A [128 x 528B] @0, B double buffer 2 x [128 x 528B] @67584, sqm 2x128f @202752.
// Ssc overlays B[cur] (128 floats = 512B fit in the 528B row).
#define KROWB 528
#define KTILE 67584            // 128 * 528
#define KS_B   67584
#define KS_SQM 202752
#define KNN_SMEM 203776
#define NCHUNK 16              // 2048 cols per CTA / 128
#define KNT 512

__device__ __forceinline__ void knn_issueB(int b, int m0, uint32_t bufAddr, uint32_t sqmAddr, int tid) {
    const uint4* abG = (const uint4*)g_ab;
    #pragma unroll 2
    for (int i = tid; i < 128 * 32; i += KNT) {
        int r = i >> 5, j = i & 31;
        cp16(bufAddr + (unsigned)(r * 33 + j) * 16, abG + (size_t)(b * NPTS + m0 + r) * 32 + j);
    }
    if (tid < 32)
        cp16(sqmAddr + tid * 16, g_sq + b * NPTS + m0 + tid * 4);
    CP_COMMIT();
}

__global__ void __launch_bounds__(KNT, 1)
knn_kernel() {
    extern __shared__ char smraw[];
    const uint32_t smem_base = (uint32_t)__cvta_generic_to_shared(smraw);
    const uint32_t asAddr  = smem_base;
    const uint32_t bAddr0  = smem_base + KS_B;
    const uint32_t sqmAddr = smem_base + KS_SQM;
    float* sqmF = (float*)(smraw + KS_SQM);

    const int tid = threadIdx.x, wid = tid >> 5, l = tid & 31;
    const int b = blockIdx.z, half = blockIdx.y, n0 = blockIdx.x * 128;
    const int colBase = half * 2048;

    // prologue: A tile + B chunk0 + sqm0, one cp.async group
    {
        const uint4* abG = (const uint4*)g_ab;
        #pragma unroll 2
        for (int i = tid; i < 128 * 32; i += KNT) {
            int r = i >> 5, j = i & 31;
            cp16(asAddr + (unsigned)(r * 33 + j) * 16, abG + (size_t)(b * NPTS + n0 + r) * 32 + j);
        }
    }
    knn_issueB(b, colBase, bAddr0, sqmAddr, tid);

    const int wm = wid & 3, wn = wid >> 2;        // 4x4 warp grid, warp tile 32x32
    const int g = l >> 2, t = l & 3;
    const int rB = tid >> 2, cs = tid & 3;        // topk: 4 threads per row, 32 cols each

    // per-thread ldsm fragment bases (padded layout: plain strides, no swizzle)
    const uint32_t aFrag = asAddr + (unsigned)(wm * 32 + (l & 15)) * KROWB + (unsigned)(l >> 4) * 16;
    const uint32_t bFragOff = (unsigned)(wn * 32 + (l >> 4) * 8 + (l & 7)) * KROWB
                            + (unsigned)((l >> 3) & 1) * 16;

    // top-9 as sorted float values + int indices (FSETP/FSEL on fma pipe, int SEL on alu)
    float tv[9];
    int   tix[9];
    #pragma unroll
    for (int i = 0; i < 9; ++i) { tv[i] = -3.402823466e38f; tix[i] = 0x7FFFFFFF; }

    for (int chunk = 0; chunk < NCHUNK; ++chunk) {
        const int cur = chunk & 1;
        const int m0  = colBase + chunk * 128;

        CP_WAIT0();          // B[cur] + sqm[cur] resident
        __syncthreads();     // everyone sees it; prev Ssc (in B[1-cur]) reads done

        if (chunk + 1 < NCHUNK)   // next load -> B[1-cur], overlaps MMA+scatter+topk
            knn_issueB(b, m0 + 128, bAddr0 + (unsigned)(1 - cur) * KTILE,
                       sqmAddr + (unsigned)(1 - cur) * 512, tid);

        const uint32_t bFrag = bAddr0 + (unsigned)cur * KTILE + bFragOff;

        float acc[2][4][4];
        #pragma unroll
        for (int mi = 0; mi < 2; ++mi)
            #pragma unroll
            for (int ni = 0; ni < 4; ++ni)
                #pragma unroll
                for (int q = 0; q < 4; ++q) acc[mi][ni][q] = 0.f;

        // emulated-fp32 K=384 with hi/lo fragment REUSE:
        // per kk: load aHi,bHi -> (hi,hi); load bLo -> (hi,lo); load aLo -> (lo,hi)
        #pragma unroll
        for (int kk = 0; kk < 8; ++kk) {
            uint32_t aHi[2][4], aLo[2][4], bHi[2][4], bLo[2][4];
            #pragma unroll
            for (int mi = 0; mi < 2; ++mi)
                ldsm4(aHi[mi], aFrag + (unsigned)(mi * 16 * KROWB) + kk * 32);
            ldsm4(bHi[0], bFrag + kk * 32);
            ldsm4(bHi[1], bFrag + 16 * KROWB + kk * 32);
            #pragma unroll
            for (int mi = 0; mi < 2; ++mi) {   // (hi, hi)
                mma_bf16(acc[mi][0], aHi[mi][0], aHi[mi][1], aHi[mi][2], aHi[mi][3], bHi[0][0], bHi[0][1]);
                mma_bf16(acc[mi][1], aHi[mi][0], aHi[mi][1], aHi[mi][2], aHi[mi][3], bHi[0][2], bHi[0][3]);
                mma_bf16(acc[mi][2], aHi[mi][0], aHi[mi][1], aHi[mi][2], aHi[mi][3], bHi[1][0], bHi[1][1]);
                mma_bf16(acc[mi][3], aHi[mi][0], aHi[mi][1], aHi[mi][2], aHi[mi][3], bHi[1][2], bHi[1][3]);
            }
            ldsm4(bLo[0], bFrag + 256 + kk * 32);
            ldsm4(bLo[1], bFrag + 16 * KROWB + 256 + kk * 32);
            #pragma unroll
            for (int mi = 0; mi < 2; ++mi) {   // (hi, lo)
                mma_bf16(acc[mi][0], aHi[mi][0], aHi[mi][1], aHi[mi][2], aHi[mi][3], bLo[0][0], bLo[0][1]);
                mma_bf16(acc[mi][1], aHi[mi][0], aHi[mi][1], aHi[mi][2], aHi[mi][3], bLo[0][2], bLo[0][3]);
                mma_bf16(acc[mi][2], aHi[mi][0], aHi[mi][1], aHi[mi][2], aHi[mi][3], bLo[1][0], bLo[1][1]);
                mma_bf16(acc[mi][3], aHi[mi][0], aHi[mi][1], aHi[mi][2], aHi[mi][3], bLo[1][2], bLo[1][3]);
            }
            #pragma unroll
            for (int mi = 0; mi < 2; ++mi)
                ldsm4(aLo[mi], aFrag + (unsigned)(mi * 16 * KROWB) + 256 + kk * 32);
            #pragma unroll
            for (int mi = 0; mi < 2; ++mi) {   // (lo, hi)
                mma_bf16(acc[mi][0], aLo[mi][0], aLo[mi][1], aLo[mi][2], aLo[mi][3], bHi[0][0], bHi[0][1]);
                mma_bf16(acc[mi][1], aLo[mi][0], aLo[mi][1], aLo[mi][2], aLo[mi][3], bHi[0][2], bHi[0][3]);
                mma_bf16(acc[mi][2], aLo[mi][0], aLo[mi][1], aLo[mi][2], aLo[mi][3], bHi[1][0], bHi[1][1]);
                mma_bf16(acc[mi][3], aLo[mi][0], aLo[mi][1], aLo[mi][2], aLo[mi][3], bHi[1][2], bHi[1][3]);
            }
        }

        __syncthreads();     // all MMA reads of B[cur] done -> Ssc may overlay it

        // scatter rank values (2*inner - sq_m; -sq_r is row-constant, rank-invariant)
        char* ssc = smraw + KS_B + (size_t)cur * KTILE;
        const float* sqc = sqmF + cur * 128;
        #pragma unroll
        for (int mi = 0; mi < 2; ++mi) {
            int r0 = wm * 32 + mi * 16 + g;
            #pragma unroll
            for (int ni = 0; ni < 4; ++ni) {
                int C = wn * 32 + ni * 8 + t * 2;
                float2 sm2 = *(const float2*)&sqc[C];
                float* a = acc[mi][ni];
                *(float2*)(ssc + r0 * KROWB + C * 4) =
                    make_float2(fmaf(2.f, a[0], -sm2.x), fmaf(2.f, a[1], -sm2.y));
                *(float2*)(ssc + (r0 + 8) * KROWB + C * 4) =
                    make_float2(fmaf(2.f, a[2], -sm2.x), fmaf(2.f, a[3], -sm2.y));
            }
        }
        __syncthreads();

        // top-9: float/idx sorted insert over 32 cols of this thread's fixed row.
        // Strict '>' keeps first-seen (= lowest idx) on ties, matching packKey order.
        const char* srow = ssc + rB * KROWB + cs * 128;
        #pragma unroll
        for (int j4 = 0; j4 < 8; ++j4) {
            const float4 v = *(const float4*)(srow + j4 * 16);
            float m4 = fmaxf(fmaxf(v.x, v.y), fmaxf(v.z, v.w));
            if (m4 > tv[8]) {
                float vv[4] = {v.x, v.y, v.z, v.w};
                #pragma unroll
                for (int q = 0; q < 4; ++q) {
                    float cv = vv[q];
                    if (cv > tv[8]) {
                        int ci = m0 + cs * 32 + j4 * 4 + q;
                        #pragma unroll
                        for (int i = 0; i < 9; ++i) {
                            bool gg = cv > tv[i];
                            float nv = gg ? cv : tv[i];
                            int   nx = gg ? ci : tix[i];
                            cv = gg ? tv[i] : cv;
                            ci = gg ? tix[i] : ci;
                            tv[i] = nv; tix[i] = nx;
                        }
                    }
                }
            }
        }
    }

    // build u64 keys and merge the four col-slices of each row (4-lane shfl segments)
    unsigned long long tk[9];
    #pragma unroll
    for (int k = 0; k < KNB; ++k) tk[k] = packKey(tv[k], (unsigned)tix[k]);

    for (int k = 0; k < KNB; ++k) {
        unsigned long long m = tk[0];
        #pragma unroll
        for (int d = 2; d; d >>= 1) {
            unsigned long long o = __shfl_down_sync(0xffffffffu, m, d, 4);
            if (o > m) m = o;
        }
        m = __shfl_sync(0xffffffffu, m, 0, 4);
        if (tk[0] == m) {    // keys unique: exactly one lane pops
            #pragma unroll
            for (int i = 0; i < 8; ++i) tk[i] = tk[i + 1];
            tk[8] = 0ull;
        }
        if (cs == 0)
            g_nnk[((size_t)(b * 2 + half) * NPTS + n0 + rB) * KNB + k] = m;
    }
}

// ---------------- merge the two column-halves' top-9 lists ----------------
__global__ void nnmerge_kernel() {
    int i = blockIdx.x * 256 + threadIdx.x;
    if (i >= BB * NPTS) return;
    int b = i >> 12, row = i & (NPTS - 1);
    const unsigned long long* k0 = g_nnk + ((size_t)(b * 2 + 0) * NPTS + row) * KNB;
    const unsigned long long* k1 = g_nnk + ((size_t)(b * 2 + 1) * NPTS + row) * KNB;
    unsigned long long tk[9];
    #pragma unroll
    for (int k = 0; k < KNB; ++k) tk[k] = k0[k];
    #pragma unroll
    for (int k = 0; k < KNB; ++k) tkInsert(tk, k1[k]);
    #pragma unroll
    for (int k = 0; k < KNB; ++k)
        g_nn[(b * NPTS + row) * KNB + k] = (int)(0xFFFFFFFFu - (unsigned)tk[k]);
}

// ================= p/q GEMM (round-7 proven): y[b][n][o] = (wct[o].xn[n])*nrm[n] =================
#define KM   64
#define KN   128
#define KSTR 264

__device__ __forceinline__ void gmma_block(float acc[2][4][4], uint32_t aAddr, uint32_t bAddr) {
    #pragma unroll
    for (int seg = 0; seg < 3; ++seg) {
        const int aoff = (seg == 2) ? 256 : 0;
        const int boff = (seg == 1) ? 256 : 0;
        #pragma unroll
        for (int kk = 0; kk < 8; ++kk) {
            uint32_t a[2][4], bq[2][4];
            ldsm4(a[0], aAddr + aoff + kk * 32);
            ldsm4(a[1], aAddr + 16 * KROWB + aoff + kk * 32);
            ldsm4(bq[0], bAddr + boff + kk * 32);
            ldsm4(bq[1], bAddr + 16 * KROWB + boff + kk * 32);
            #pragma unroll
            for (int mi = 0; mi < 2; ++mi) {
                mma_bf16(acc[mi][0], a[mi][0], a[mi][1], a[mi][2], a[mi][3], bq[0][0], bq[0][1]);
                mma_bf16(acc[mi][1], a[mi][0], a[mi][1], a[mi][2], a[mi][3], bq[0][2], bq[0][3]);
                mma_bf16(acc[mi][2], a[mi][0], a[mi][1], a[mi][2], a[mi][3], bq[1][0], bq[1][1]);
                mma_bf16(acc[mi][3], a[mi][0], a[mi][1], a[mi][2], a[mi][3], bq[1][2], bq[1][3]);
            }
        }
    }
}
__device__ __forceinline__ void gemm_issueW(int o0, uint32_t bsAddr, int tid) {
    const uint4* wbG = (const uint4*)g_wb;
    #pragma unroll 4
    for (int i = tid; i < KN * 32; i += 256) {
        int r = i >> 5, j = i & 31;
        cp16(bsAddr + (unsigned)(r * 33 + j) * 16, wbG + (size_t)(o0 + r) * 32 + j);
    }
    CP_COMMIT();
}

__global__ void __launch_bounds__(256, 1)
gemm_kernel() {
    extern __shared__ char smraw[];
    __nv_bfloat16* As  = (__nv_bfloat16*)smraw;       // [64][264]  (points)
    __nv_bfloat16* Bs0 = As + KM * KSTR;              // 2 x [128][264] (wct)
    float* nrmr = (float*)(Bs0 + 2 * KN * KSTR);      // [64]

    const int tid = threadIdx.x;
    const int b   = blockIdx.y;
    const int n0  = blockIdx.x * KM;
    const uint4* __restrict__ abG = (const uint4*)g_ab;

    const uint32_t asAddr  = (uint32_t)__cvta_generic_to_shared(As);
    const uint32_t bsAddr0 = (uint32_t)__cvta_generic_to_shared(Bs0);
    gemm_issueW(0, bsAddr0, tid);

    for (int i = tid; i < KM * 32; i += 256) {
        int r = i >> 5, j = i & 31;
        ((uint4*)As)[r * 33 + j] = abG[(size_t)(b * NPTS + n0 + r) * 32 + j];
    }
    if (tid < KM) nrmr[tid] = g_nrm[b * NPTS + n0 + tid];

    const int wid = tid >> 5, l = tid & 31;
    const int wm = wid & 1, wn = wid >> 1;
    const int g = l >> 2, t = l & 3;

    const uint32_t aFrag = asAddr + (unsigned)(wm * 32 + (l & 15)) * KROWB + (unsigned)(l >> 4) * 16;
    const uint32_t bFragOff = (unsigned)(wn * 32 + (l >> 4) * 8 + (l & 7)) * KROWB
                            + (unsigned)((l >> 3) & 1) * 16;

    float* yb = g_y + (size_t)b * NPTS * OC2;

    for (int chunk = 0; chunk < OC2 / KN; ++chunk) {
        const int cur = chunk & 1;
        CP_WAIT0();
        __syncthreads();
        if (chunk + 1 < OC2 / KN)
            gemm_issueW((chunk + 1) * KN, bsAddr0 + (unsigned)(1 - cur) * KN * KSTR * 2, tid);

        float acc[2][4][4];
        #pragma unroll
        for (int mi = 0; mi < 2; ++mi)
            #pragma unroll
            for (int ni = 0; ni < 4; ++ni)
                #pragma unroll
                for (int q = 0; q < 4; ++q) acc[mi][ni][q] = 0.f;

        gmma_block(acc, aFrag, bsAddr0 + (unsigned)cur * KN * KSTR * 2 + bFragOff);

        const int oc = chunk * KN;
        #pragma unroll
        for (int mi = 0; mi < 2; ++mi) {
            int r = wm * 32 + mi * 16 + g;
            float nr0 = nrmr[r], nr1 = nrmr[r + 8];
            #pragma unroll
            for (int ni = 0; ni < 4; ++ni) {
                int c = wn * 32 + ni * 8 + t * 2;
                float* a = acc[mi][ni];
                *(float2*)&yb[(size_t)(n0 + r) * OC2 + oc + c] =
                    make_float2(a[0] * nr0, a[1] * nr0);
                *(float2*)&yb[(size_t)(n0 + r + 8) * OC2 + oc + c] =
                    make_float2(a[2] * nr1, a[3] * nr1);
            }
        }
        __syncthreads();
    }
}

// ---------------- epilogue: gather + max + relu ----------------
__global__ void final_kernel(const float* __restrict__ bias, float* __restrict__ out) {
    __shared__ int sj[KNB];
    const int n = blockIdx.x;
    const int b = blockIdx.y;
    const int o = threadIdx.x;
    if (o < KNB) sj[o] = g_nn[(b * NPTS + n) * KNB + o];
    __syncthreads();
    const float* yb = g_y + (size_t)b * NPTS * OC2;
    float p = yb[(size_t)n * OC2 + o];
    float best = -3.4e38f;
    #pragma unroll
    for (int k = 0; k < KNB; ++k)
        best = fmaxf(best, yb[(size_t)sj[k] * OC2 + OC + o]);
    float v = fmaxf(p + best + bias[o], 0.f);
    out[((size_t)b * OC + o) * NPTS + n] = v;
}

// ---------------- launch ----------------
extern "C" void kernel_launch(void* const* d_in, const int* in_sizes, int n_in,
                              void* d_out, int out_size) {
    const float* x    = (const float*)d_in[0];
    const float* w    = (const float*)d_in[1];
    const float* bias = (const float*)d_in[2];
    float* out = (float*)d_out;

    const int prep_smem = (128 * 129 + 128) * (int)sizeof(float);       // 66560
    const int gemm_smem = KM*KSTR*2 + 2*KN*KSTR*2 + KM * 4;             // 169216
    cudaFuncSetAttribute(prep_kernel, cudaFuncAttributeMaxDynamicSharedMemorySize, prep_smem);
    cudaFuncSetAttribute(knn_kernel,  cudaFuncAttributeMaxDynamicSharedMemorySize, KNN_SMEM);
    cudaFuncSetAttribute(gemm_kernel, cudaFuncAttributeMaxDynamicSharedMemorySize, gemm_smem);

    prep_kernel   <<<dim3(NPTS / 128, BB), 128, prep_smem>>>(x);
    wprep_kernel  <<<(OC2 * CCH + 255) / 256, 256>>>(w);
    gemm_kernel   <<<dim3(NPTS / KM, BB), 256, gemm_smem>>>();
    knn_kernel    <<<dim3(NPTS / 128, 2, BB), KNT, KNN_SMEM>>>();
    nnmerge_kernel<<<(BB * NPTS + 255) / 256, 256>>>();
    final_kernel  <<<dim3(NPTS, BB), 256>>>(bias, out);
}